// round 1
// baseline (speedup 1.0000x reference)
#include <cuda_runtime.h>
#include <math_constants.h>

#define BATCH 4
#define SEQT 4096
#define EMB 768
#define HD 64
#define BT (BATCH * SEQT)

// Scratch for projections (device globals: no allocation allowed)
__device__ float g_q[BT * HD];
__device__ float g_k[BT * HD];
__device__ float g_v[BT * HD];

// ---------------------------------------------------------------------------
// Projection: out = x @ W for W in {Wq, Wk, Wv}.
// grid = (BT/64, 3), block = 256 (16x16 threads), each thread owns a 4x4 tile.
// ---------------------------------------------------------------------------
__global__ __launch_bounds__(256) void proj_kernel(
    const float* __restrict__ x,
    const float* __restrict__ Wq,
    const float* __restrict__ Wk,
    const float* __restrict__ Wv)
{
    const float* W;
    float* out;
    if (blockIdx.y == 0)      { W = Wq; out = g_q; }
    else if (blockIdx.y == 1) { W = Wk; out = g_k; }
    else                      { W = Wv; out = g_v; }

    __shared__ float xs[64][36];  // 64 rows x 32 k (pad to 36 for float4-aligned stores)
    __shared__ float ws[32][64];  // 32 k x 64 cols

    const int tid = threadIdx.x;
    const int tx = tid & 15, ty = tid >> 4;
    const int row0 = blockIdx.x * 64;

    float acc[4][4] = {};

    for (int k0 = 0; k0 < EMB; k0 += 32) {
        // load x tile: 64 rows x 32 floats = 512 float4
        #pragma unroll
        for (int it = 0; it < 2; it++) {
            int i = tid + it * 256;
            int r = i >> 3, c = i & 7;
            float4 v = *reinterpret_cast<const float4*>(
                &x[(size_t)(row0 + r) * EMB + k0 + c * 4]);
            *reinterpret_cast<float4*>(&xs[r][c * 4]) = v;
        }
        // load W tile: 32 k x 64 cols = 512 float4
        #pragma unroll
        for (int it = 0; it < 2; it++) {
            int i = tid + it * 256;
            int kk = i >> 4, c = i & 15;
            float4 v = *reinterpret_cast<const float4*>(
                &W[(size_t)(k0 + kk) * HD + c * 4]);
            *reinterpret_cast<float4*>(&ws[kk][c * 4]) = v;
        }
        __syncthreads();

        #pragma unroll 8
        for (int kk = 0; kk < 32; kk++) {
            float xf[4];
            #pragma unroll
            for (int i = 0; i < 4; i++) xf[i] = xs[ty * 4 + i][kk];
            float4 w4 = *reinterpret_cast<float4*>(&ws[kk][tx * 4]);
            #pragma unroll
            for (int i = 0; i < 4; i++) {
                acc[i][0] += xf[i] * w4.x;
                acc[i][1] += xf[i] * w4.y;
                acc[i][2] += xf[i] * w4.z;
                acc[i][3] += xf[i] * w4.w;
            }
        }
        __syncthreads();
    }

    #pragma unroll
    for (int i = 0; i < 4; i++) {
        float4 v = make_float4(acc[i][0], acc[i][1], acc[i][2], acc[i][3]);
        *reinterpret_cast<float4*>(
            &out[(size_t)(row0 + ty * 4 + i) * HD + tx * 4]) = v;
    }
}

// ---------------------------------------------------------------------------
// Flash attention (causal), fp32. grid = (T/64, B), block = 256.
// Per block: one 64-row Q tile; stream K/V tiles 0..qi with online softmax.
// Thread (ty,tx) in 16x16 grid owns S rows ty*4..+3, cols tx*4..+3 and
// O rows ty*4..+3, dims tx*4..+3.
// K is stored transposed + XOR-swizzled (float4 groups) for conflict-free QK^T.
// ---------------------------------------------------------------------------
#define ATTN_SMEM_FLOATS (4096 * 3 + 64 * 68)
#define ATTN_SMEM_BYTES (ATTN_SMEM_FLOATS * 4)

__global__ __launch_bounds__(256, 2) void attn_kernel(float* __restrict__ out)
{
    extern __shared__ float sm[];
    float* Qs = sm;             // [64][64]  (pre-scaled by 1/8)
    float* Kt = sm + 4096;      // [64][64]  Kt[d][n], n-groups XOR-swizzled by d&15
    float* Vs = sm + 8192;      // [64][64]
    float* Ps = sm + 12288;     // [64][68]

    const int tid = threadIdx.x;
    const int tx = tid & 15, ty = tid >> 4;
    const int qi = (SEQT / 64 - 1) - blockIdx.x;  // heavy tiles first
    const int b = blockIdx.y;

    const float* Qg = g_q + ((size_t)b * SEQT + qi * 64) * HD;

    // Load Q tile, pre-scaled by 1/sqrt(HD)
    for (int i = tid; i < 64 * 16; i += 256) {
        float4 v = reinterpret_cast<const float4*>(Qg)[i];
        v.x *= 0.125f; v.y *= 0.125f; v.z *= 0.125f; v.w *= 0.125f;
        reinterpret_cast<float4*>(Qs)[i] = v;
    }

    float row_max[4], row_sum[4], o[4][4];
    #pragma unroll
    for (int i = 0; i < 4; i++) {
        row_max[i] = -CUDART_INF_F;
        row_sum[i] = 0.0f;
        #pragma unroll
        for (int j = 0; j < 4; j++) o[i][j] = 0.0f;
    }

    for (int kt = 0; kt <= qi; kt++) {
        const float* Kg = g_k + ((size_t)b * SEQT + kt * 64) * HD;
        const float* Vg = g_v + ((size_t)b * SEQT + kt * 64) * HD;

        __syncthreads();  // previous iteration's P/V reads done before overwrite

        // Load K (transposed+swizzled) and V (row-major)
        for (int i = tid; i < 64 * 16; i += 256) {
            int n = i >> 4, d4 = i & 15;
            float4 kv = reinterpret_cast<const float4*>(Kg)[i];
            int g = n >> 2, lo = n & 3;
            int d0 = d4 * 4;
            Kt[(d0 + 0) * 64 + ((g ^ ((d0 + 0) & 15)) << 2) + lo] = kv.x;
            Kt[(d0 + 1) * 64 + ((g ^ ((d0 + 1) & 15)) << 2) + lo] = kv.y;
            Kt[(d0 + 2) * 64 + ((g ^ ((d0 + 2) & 15)) << 2) + lo] = kv.z;
            Kt[(d0 + 3) * 64 + ((g ^ ((d0 + 3) & 15)) << 2) + lo] = kv.w;
            float4 vv = reinterpret_cast<const float4*>(Vg)[i];
            reinterpret_cast<float4*>(Vs)[i] = vv;
        }
        __syncthreads();

        // S = Q K^T (Q already scaled)
        float s[4][4] = {};
        #pragma unroll 4
        for (int d = 0; d < 64; d++) {
            float4 k4 = *reinterpret_cast<float4*>(
                &Kt[(d << 6) + ((tx ^ (d & 15)) << 2)]);
            #pragma unroll
            for (int i = 0; i < 4; i++) {
                float qf = Qs[((ty * 4 + i) << 6) + d];
                s[i][0] += qf * k4.x;
                s[i][1] += qf * k4.y;
                s[i][2] += qf * k4.z;
                s[i][3] += qf * k4.w;
            }
        }

        // Causal mask on the diagonal tile
        if (kt == qi) {
            #pragma unroll
            for (int i = 0; i < 4; i++)
                #pragma unroll
                for (int j = 0; j < 4; j++)
                    if (tx * 4 + j > ty * 4 + i) s[i][j] = -CUDART_INF_F;
        }

        // Online softmax: row reductions over the 16-lane tx group
        #pragma unroll
        for (int i = 0; i < 4; i++) {
            float m = fmaxf(fmaxf(s[i][0], s[i][1]), fmaxf(s[i][2], s[i][3]));
            m = fmaxf(m, __shfl_xor_sync(0xffffffffu, m, 1, 16));
            m = fmaxf(m, __shfl_xor_sync(0xffffffffu, m, 2, 16));
            m = fmaxf(m, __shfl_xor_sync(0xffffffffu, m, 4, 16));
            m = fmaxf(m, __shfl_xor_sync(0xffffffffu, m, 8, 16));
            float nm = fmaxf(row_max[i], m);           // finite: tile 0 is unmasked
            float alpha = __expf(row_max[i] - nm);     // exp(-inf)=0 on first tile
            row_max[i] = nm;

            float p0 = __expf(s[i][0] - nm);
            float p1 = __expf(s[i][1] - nm);
            float p2 = __expf(s[i][2] - nm);
            float p3 = __expf(s[i][3] - nm);
            float ts = (p0 + p1) + (p2 + p3);
            ts += __shfl_xor_sync(0xffffffffu, ts, 1, 16);
            ts += __shfl_xor_sync(0xffffffffu, ts, 2, 16);
            ts += __shfl_xor_sync(0xffffffffu, ts, 4, 16);
            ts += __shfl_xor_sync(0xffffffffu, ts, 8, 16);
            row_sum[i] = row_sum[i] * alpha + ts;

            o[i][0] *= alpha; o[i][1] *= alpha; o[i][2] *= alpha; o[i][3] *= alpha;

            *reinterpret_cast<float4*>(&Ps[(ty * 4 + i) * 68 + tx * 4]) =
                make_float4(p0, p1, p2, p3);
        }
        __syncthreads();

        // O += P @ V
        #pragma unroll 4
        for (int nn = 0; nn < 16; nn++) {
            float4 pr[4];
            #pragma unroll
            for (int i = 0; i < 4; i++)
                pr[i] = *reinterpret_cast<float4*>(&Ps[(ty * 4 + i) * 68 + nn * 4]);
            #pragma unroll
            for (int l = 0; l < 4; l++) {
                float4 v4 = *reinterpret_cast<float4*>(
                    &Vs[((nn * 4 + l) << 6) + tx * 4]);
                #pragma unroll
                for (int i = 0; i < 4; i++) {
                    float p = reinterpret_cast<float*>(&pr[i])[l];
                    o[i][0] += p * v4.x;
                    o[i][1] += p * v4.y;
                    o[i][2] += p * v4.z;
                    o[i][3] += p * v4.w;
                }
            }
        }
    }

    // Epilogue: normalize and store
    #pragma unroll
    for (int i = 0; i < 4; i++) {
        float inv = 1.0f / row_sum[i];
        float4 r = make_float4(o[i][0] * inv, o[i][1] * inv,
                               o[i][2] * inv, o[i][3] * inv);
        size_t row = (size_t)b * SEQT + qi * 64 + ty * 4 + i;
        *reinterpret_cast<float4*>(&out[row * HD + tx * 4]) = r;
    }
}

extern "C" void kernel_launch(void* const* d_in, const int* in_sizes, int n_in,
                              void* d_out, int out_size) {
    (void)in_sizes; (void)n_in; (void)out_size;
    const float* x  = (const float*)d_in[0];
    const float* Wk = (const float*)d_in[1];
    const float* Wq = (const float*)d_in[2];
    const float* Wv = (const float*)d_in[3];
    float* out = (float*)d_out;

    dim3 pg(BT / 64, 3);
    proj_kernel<<<pg, 256>>>(x, Wq, Wk, Wv);

    cudaFuncSetAttribute(attn_kernel,
                         cudaFuncAttributeMaxDynamicSharedMemorySize,
                         ATTN_SMEM_BYTES);
    dim3 ag(SEQT / 64, BATCH);
    attn_kernel<<<ag, 256, ATTN_SMEM_BYTES>>>(out);
}

// round 3
// speedup vs baseline: 1.4407x; 1.4407x over previous
#include <cuda_runtime.h>
#include <math_constants.h>
#include <cstdint>

#define BATCH 4
#define SEQT 4096
#define EMB 768
#define HD 64
#define BT (BATCH * SEQT)

typedef unsigned long long ull;

// Scratch (device globals: no allocation allowed)
__device__ float g_q[BT * HD];
__device__ float g_k[BT * HD];
__device__ float g_v[BT * HD];
__device__ float g_po[2][BT * HD];  // split-K partial numerators
__device__ float g_pm[2][BT];       // split-K partial row max
__device__ float g_pl[2][BT];       // split-K partial row sum

// ---- f32x2 packed-math helpers (Blackwell FFMA2) ----
__device__ __forceinline__ void ffma2(ull& d, ull a, ull b) {
    asm("fma.rn.f32x2 %0, %1, %2, %0;" : "+l"(d) : "l"(a), "l"(b));
}
__device__ __forceinline__ void fmul2(ull& d, ull a, ull b) {
    asm("mul.rn.f32x2 %0, %1, %2;" : "=l"(d) : "l"(a), "l"(b));
}
__device__ __forceinline__ ull dup2(float x) {
    ull r; asm("mov.b64 %0, {%1, %1};" : "=l"(r) : "f"(x)); return r;
}
__device__ __forceinline__ float hadd2(ull s) {
    float lo, hi; asm("mov.b64 {%0, %1}, %2;" : "=f"(lo), "=f"(hi) : "l"(s));
    return lo + hi;
}
__device__ __forceinline__ void unpack2(ull s, float& lo, float& hi) {
    asm("mov.b64 {%0, %1}, %2;" : "=f"(lo), "=f"(hi) : "l"(s));
}
__device__ __forceinline__ uint32_t s2u(const void* p) {
    return (uint32_t)__cvta_generic_to_shared(p);
}
__device__ __forceinline__ void cp16(uint32_t dst, const void* src) {
    asm volatile("cp.async.ca.shared.global [%0], [%1], 16;" :: "r"(dst), "l"(src));
}

// ---------------------------------------------------------------------------
// Fused projection: q,k,v = x @ {Wq,Wk,Wv}. x tile loaded once, 3 accumulators.
// grid = BT/64, block = 256 (16x16), thread tile = 4 rows x 4 cols x 3 mats.
// f32x2 packed over the output-column pairs.
// ---------------------------------------------------------------------------
__global__ __launch_bounds__(256) void proj_kernel(
    const float* __restrict__ x,
    const float* __restrict__ Wq,
    const float* __restrict__ Wk,
    const float* __restrict__ Wv)
{
    __shared__ float xs[64][36];
    __shared__ float ws[3][32][64];

    const int tid = threadIdx.x;
    const int tx = tid & 15, ty = tid >> 4;
    const int row0 = blockIdx.x * 64;

    ull acc[3][4][2];
    #pragma unroll
    for (int m = 0; m < 3; m++)
        #pragma unroll
        for (int i = 0; i < 4; i++) { acc[m][i][0] = 0ull; acc[m][i][1] = 0ull; }

    for (int k0 = 0; k0 < EMB; k0 += 32) {
        __syncthreads();
        #pragma unroll
        for (int t = 0; t < 2; t++) {
            int i = tid + t * 256;
            int r = i >> 3, c = i & 7;
            *reinterpret_cast<float4*>(&xs[r][c * 4]) =
                *reinterpret_cast<const float4*>(&x[(size_t)(row0 + r) * EMB + k0 + c * 4]);
        }
        #pragma unroll
        for (int t = 0; t < 6; t++) {
            int i = tid + t * 256;
            int m = i >> 9, rem = i & 511, kk = rem >> 4, c = rem & 15;
            const float* W = (m == 0) ? Wq : ((m == 1) ? Wk : Wv);
            *reinterpret_cast<float4*>(&ws[m][kk][c * 4]) =
                *reinterpret_cast<const float4*>(&W[(size_t)(k0 + kk) * HD + c * 4]);
        }
        __syncthreads();

        #pragma unroll 2
        for (int kg = 0; kg < 8; kg++) {
            float4 xr[4];
            #pragma unroll
            for (int i = 0; i < 4; i++)
                xr[i] = *reinterpret_cast<float4*>(&xs[ty * 4 + i][kg * 4]);
            #pragma unroll
            for (int l = 0; l < 4; l++) {
                ull xd[4];
                #pragma unroll
                for (int i = 0; i < 4; i++)
                    xd[i] = dup2(reinterpret_cast<float*>(&xr[i])[l]);
                #pragma unroll
                for (int m = 0; m < 3; m++) {
                    ulonglong2 w = *reinterpret_cast<ulonglong2*>(&ws[m][kg * 4 + l][tx * 4]);
                    #pragma unroll
                    for (int i = 0; i < 4; i++) {
                        ffma2(acc[m][i][0], xd[i], w.x);
                        ffma2(acc[m][i][1], xd[i], w.y);
                    }
                }
            }
        }
    }

    #pragma unroll
    for (int m = 0; m < 3; m++) {
        float* op = (m == 0) ? g_q : ((m == 1) ? g_k : g_v);
        #pragma unroll
        for (int i = 0; i < 4; i++) {
            float c0, c1, c2, c3;
            unpack2(acc[m][i][0], c0, c1);
            unpack2(acc[m][i][1], c2, c3);
            *reinterpret_cast<float4*>(&op[(size_t)(row0 + ty * 4 + i) * HD + tx * 4]) =
                make_float4(c0, c1, c2, c3);
        }
    }
}

// ---------------------------------------------------------------------------
// Flash attention (causal), fp32 via f32x2, split-K for qi>=32.
// grid = (96, B): i<64 -> split blocks (qi = 63 - i/2, part = i&1),
//                 i>=64 -> unsplit (qi = 95 - i). block = 256 (16x16), 4x4 tiles.
// K/V loaded via cp.async double buffer, row-major with XOR column-group
// swizzle (group g stored at g ^ (row>>2)) for conflict-free LDS.128.
// ---------------------------------------------------------------------------
#define ATTN_SMEM_FLOATS (4096 + 8192 + 8192 + 64 * 68)
#define ATTN_SMEM_BYTES (ATTN_SMEM_FLOATS * 4)

__device__ __forceinline__ void tile_cp(float* Kb, float* Vb,
                                        const float* Kg, const float* Vg, int tid)
{
    #pragma unroll
    for (int t = 0; t < 4; t++) {
        int c = tid + t * 256;
        int row = c >> 4, g = c & 15;
        int d = (g ^ (row >> 2)) << 2;
        cp16(s2u(Kb + row * 64 + d), Kg + row * 64 + g * 4);
    }
    #pragma unroll
    for (int t = 0; t < 4; t++) {
        int c = tid + t * 256;
        int row = c >> 4, g = c & 15;
        int d = (g ^ (row >> 2)) << 2;
        cp16(s2u(Vb + row * 64 + d), Vg + row * 64 + g * 4);
    }
    asm volatile("cp.async.commit_group;" ::: "memory");
}

__global__ __launch_bounds__(256, 2) void attn_kernel(float* __restrict__ out)
{
    extern __shared__ float sm[];
    float* Qs = sm;              // [64][64]
    float* Kd = sm + 4096;       // 2 x [64][64] swizzled
    float* Vd = sm + 12288;      // 2 x [64][64] swizzled
    float* Ps = sm + 20480;      // [64][68]

    const int tid = threadIdx.x;
    const int tx = tid & 15, ty = tid >> 4;
    const int b = blockIdx.y;
    const int i0 = blockIdx.x;

    int qi, k0t, k1t, part;
    bool partial;
    if (i0 < 64) {
        qi = 63 - (i0 >> 1);
        part = i0 & 1;
        int hs = (qi + 1) >> 1;
        if (part == 0) { k0t = 0;  k1t = hs - 1; }
        else           { k0t = hs; k1t = qi; }
        partial = true;
    } else {
        qi = 95 - i0; part = 0; k0t = 0; k1t = qi; partial = false;
    }

    const float* Kbase = g_k + (size_t)b * SEQT * HD;
    const float* Vbase = g_v + (size_t)b * SEQT * HD;

    // Prefetch first two K/V tiles
    tile_cp(Kd + (k0t & 1) * 4096, Vd + (k0t & 1) * 4096,
            Kbase + (size_t)k0t * 64 * HD, Vbase + (size_t)k0t * 64 * HD, tid);
    if (k0t + 1 <= k1t)
        tile_cp(Kd + ((k0t + 1) & 1) * 4096, Vd + ((k0t + 1) & 1) * 4096,
                Kbase + (size_t)(k0t + 1) * 64 * HD, Vbase + (size_t)(k0t + 1) * 64 * HD, tid);

    // Load Q tile (pre-scaled by 1/sqrt(HD))
    const float* Qg = g_q + ((size_t)b * SEQT + qi * 64) * HD;
    for (int i = tid; i < 1024; i += 256) {
        float4 v = reinterpret_cast<const float4*>(Qg)[i];
        v.x *= 0.125f; v.y *= 0.125f; v.z *= 0.125f; v.w *= 0.125f;
        reinterpret_cast<float4*>(Qs)[i] = v;
    }

    float rm[4], rs[4];
    ull o2[4][2];
    #pragma unroll
    for (int i = 0; i < 4; i++) {
        rm[i] = -CUDART_INF_F; rs[i] = 0.0f;
        o2[i][0] = 0ull; o2[i][1] = 0ull;
    }

    for (int kt = k0t; kt <= k1t; kt++) {
        float* Kb = Kd + (kt & 1) * 4096;
        float* Vb = Vd + (kt & 1) * 4096;

        if (kt < k1t) asm volatile("cp.async.wait_group 1;" ::: "memory");
        else          asm volatile("cp.async.wait_group 0;" ::: "memory");
        __syncthreads();

        // S = Q K^T, d-packed f32x2 accumulation
        ull s2[4][4];
        #pragma unroll
        for (int i = 0; i < 4; i++)
            #pragma unroll
            for (int j = 0; j < 4; j++) s2[i][j] = 0ull;

        #pragma unroll 4
        for (int dg = 0; dg < 16; dg++) {
            ulonglong2 q[4];
            #pragma unroll
            for (int i = 0; i < 4; i++)
                q[i] = *reinterpret_cast<ulonglong2*>(&Qs[(ty * 4 + i) * 64 + dg * 4]);
            #pragma unroll
            for (int j = 0; j < 4; j++) {
                ulonglong2 k = *reinterpret_cast<ulonglong2*>(
                    &Kb[(tx * 4 + j) * 64 + ((dg ^ tx) << 2)]);
                #pragma unroll
                for (int i = 0; i < 4; i++) {
                    ffma2(s2[i][j], q[i].x, k.x);
                    ffma2(s2[i][j], q[i].y, k.y);
                }
            }
        }

        float s[4][4];
        #pragma unroll
        for (int i = 0; i < 4; i++)
            #pragma unroll
            for (int j = 0; j < 4; j++) s[i][j] = hadd2(s2[i][j]);

        if (kt == qi) {
            #pragma unroll
            for (int i = 0; i < 4; i++)
                #pragma unroll
                for (int j = 0; j < 4; j++)
                    if (tx * 4 + j > ty * 4 + i) s[i][j] = -CUDART_INF_F;
        }

        // Online softmax (row reductions over the 16-lane tx group)
        #pragma unroll
        for (int i = 0; i < 4; i++) {
            float m = fmaxf(fmaxf(s[i][0], s[i][1]), fmaxf(s[i][2], s[i][3]));
            m = fmaxf(m, __shfl_xor_sync(0xffffffffu, m, 1, 16));
            m = fmaxf(m, __shfl_xor_sync(0xffffffffu, m, 2, 16));
            m = fmaxf(m, __shfl_xor_sync(0xffffffffu, m, 4, 16));
            m = fmaxf(m, __shfl_xor_sync(0xffffffffu, m, 8, 16));
            float nm = fmaxf(rm[i], m);
            float alpha = __expf(rm[i] - nm);
            rm[i] = nm;

            float p0 = __expf(s[i][0] - nm);
            float p1 = __expf(s[i][1] - nm);
            float p2 = __expf(s[i][2] - nm);
            float p3 = __expf(s[i][3] - nm);
            float ts = (p0 + p1) + (p2 + p3);
            ts += __shfl_xor_sync(0xffffffffu, ts, 1, 16);
            ts += __shfl_xor_sync(0xffffffffu, ts, 2, 16);
            ts += __shfl_xor_sync(0xffffffffu, ts, 4, 16);
            ts += __shfl_xor_sync(0xffffffffu, ts, 8, 16);
            rs[i] = rs[i] * alpha + ts;

            ull ad = dup2(alpha);
            fmul2(o2[i][0], o2[i][0], ad);
            fmul2(o2[i][1], o2[i][1], ad);

            *reinterpret_cast<float4*>(&Ps[(ty * 4 + i) * 68 + tx * 4]) =
                make_float4(p0, p1, p2, p3);
        }
        __syncthreads();

        // O += P @ V  (column-pair packed f32x2)
        #pragma unroll 2
        for (int ng = 0; ng < 16; ng++) {
            float4 p4[4];
            #pragma unroll
            for (int i = 0; i < 4; i++)
                p4[i] = *reinterpret_cast<float4*>(&Ps[(ty * 4 + i) * 68 + ng * 4]);
            #pragma unroll
            for (int l = 0; l < 4; l++) {
                int n = ng * 4 + l;
                ulonglong2 v = *reinterpret_cast<ulonglong2*>(
                    &Vb[n * 64 + ((tx ^ (n >> 2)) << 2)]);
                #pragma unroll
                for (int i = 0; i < 4; i++) {
                    ull pd = dup2(reinterpret_cast<float*>(&p4[i])[l]);
                    ffma2(o2[i][0], pd, v.x);
                    ffma2(o2[i][1], pd, v.y);
                }
            }
        }
        __syncthreads();

        if (kt + 2 <= k1t)
            tile_cp(Kd + (kt & 1) * 4096, Vd + (kt & 1) * 4096,
                    Kbase + (size_t)(kt + 2) * 64 * HD,
                    Vbase + (size_t)(kt + 2) * 64 * HD, tid);
    }

    if (!partial) {
        #pragma unroll
        for (int i = 0; i < 4; i++) {
            float inv = 1.0f / rs[i];
            float c0, c1, c2, c3;
            unpack2(o2[i][0], c0, c1);
            unpack2(o2[i][1], c2, c3);
            size_t row = (size_t)b * SEQT + qi * 64 + ty * 4 + i;
            *reinterpret_cast<float4*>(&out[row * HD + tx * 4]) =
                make_float4(c0 * inv, c1 * inv, c2 * inv, c3 * inv);
        }
    } else {
        #pragma unroll
        for (int i = 0; i < 4; i++) {
            int gr = b * SEQT + qi * 64 + ty * 4 + i;
            float c0, c1, c2, c3;
            unpack2(o2[i][0], c0, c1);
            unpack2(o2[i][1], c2, c3);
            *reinterpret_cast<float4*>(&g_po[part][(size_t)gr * HD + tx * 4]) =
                make_float4(c0, c1, c2, c3);
            if (tx == 0) { g_pm[part][gr] = rm[i]; g_pl[part][gr] = rs[i]; }
        }
    }
}

// ---------------------------------------------------------------------------
// Combine the two split-K partials for rows with qi >= 32 (local row >= 2048).
// 8192 rows x 16 float4 -> 131072 threads.
// ---------------------------------------------------------------------------
__global__ __launch_bounds__(256) void combine_kernel(float* __restrict__ out)
{
    int idx = blockIdx.x * 256 + threadIdx.x;
    int hr = idx >> 4;
    int c4 = (idx & 15) << 2;
    int b = hr >> 11;
    int r = 2048 + (hr & 2047);
    int gr = b * SEQT + r;

    float m0 = g_pm[0][gr], m1 = g_pm[1][gr];
    float M = fmaxf(m0, m1);
    float e0 = __expf(m0 - M), e1 = __expf(m1 - M);
    float den = e0 * g_pl[0][gr] + e1 * g_pl[1][gr];
    float inv = 1.0f / den;

    float4 a = *reinterpret_cast<float4*>(&g_po[0][(size_t)gr * HD + c4]);
    float4 c = *reinterpret_cast<float4*>(&g_po[1][(size_t)gr * HD + c4]);
    float4 o;
    o.x = (e0 * a.x + e1 * c.x) * inv;
    o.y = (e0 * a.y + e1 * c.y) * inv;
    o.z = (e0 * a.z + e1 * c.z) * inv;
    o.w = (e0 * a.w + e1 * c.w) * inv;
    *reinterpret_cast<float4*>(&out[(size_t)gr * HD + c4]) = o;
}

extern "C" void kernel_launch(void* const* d_in, const int* in_sizes, int n_in,
                              void* d_out, int out_size) {
    (void)in_sizes; (void)n_in; (void)out_size;
    const float* x  = (const float*)d_in[0];
    const float* Wk = (const float*)d_in[1];
    const float* Wq = (const float*)d_in[2];
    const float* Wv = (const float*)d_in[3];
    float* out = (float*)d_out;

    proj_kernel<<<BT / 64, 256>>>(x, Wq, Wk, Wv);

    cudaFuncSetAttribute(attn_kernel,
                         cudaFuncAttributeMaxDynamicSharedMemorySize,
                         ATTN_SMEM_BYTES);
    dim3 ag(96, BATCH);
    attn_kernel<<<ag, 256, ATTN_SMEM_BYTES>>>(out);

    combine_kernel<<<512, 256>>>(out);
}

// round 5
// speedup vs baseline: 1.5514x; 1.0769x over previous
#include <cuda_runtime.h>
#include <math_constants.h>
#include <cstdint>

#define BATCH 4
#define SEQT 4096
#define EMB 768
#define HD 64
#define BT (BATCH * SEQT)

typedef unsigned long long ull;

// Scratch (device globals: no allocation allowed)
__device__ float g_q[BT * HD];
__device__ float g_k[BT * HD];
__device__ float g_v[BT * HD];
__device__ float g_po[2][BT * HD];  // split-K partial numerators
__device__ float g_pm[2][BT];       // split-K partial row max
__device__ float g_pl[2][BT];       // split-K partial row sum

// ---- f32x2 packed-math helpers (Blackwell FFMA2) ----
__device__ __forceinline__ void ffma2(ull& d, ull a, ull b) {
    asm("fma.rn.f32x2 %0, %1, %2, %0;" : "+l"(d) : "l"(a), "l"(b));
}
__device__ __forceinline__ void fmul2(ull& d, ull a, ull b) {
    asm("mul.rn.f32x2 %0, %1, %2;" : "=l"(d) : "l"(a), "l"(b));
}
__device__ __forceinline__ ull dup2(float x) {
    ull r; asm("mov.b64 %0, {%1, %1};" : "=l"(r) : "f"(x)); return r;
}
__device__ __forceinline__ float hadd2(ull s) {
    float lo, hi; asm("mov.b64 {%0, %1}, %2;" : "=f"(lo), "=f"(hi) : "l"(s));
    return lo + hi;
}
__device__ __forceinline__ void unpack2(ull s, float& lo, float& hi) {
    asm("mov.b64 {%0, %1}, %2;" : "=f"(lo), "=f"(hi) : "l"(s));
}
__device__ __forceinline__ uint32_t s2u(const void* p) {
    return (uint32_t)__cvta_generic_to_shared(p);
}
__device__ __forceinline__ void cp16(uint32_t dst, const void* src) {
    asm volatile("cp.async.ca.shared.global [%0], [%1], 16;" :: "r"(dst), "l"(src));
}

// ---- mma.sync tf32 helpers (sm_80+ path; no 'a' features) ----
__device__ __forceinline__ uint32_t cvt_tf32(float f) {
    uint32_t r; asm("cvt.rna.tf32.f32 %0, %1;" : "=r"(r) : "f"(f)); return r;
}
__device__ __forceinline__ void hilo(float v, uint32_t& hi, uint32_t& lo) {
    hi = cvt_tf32(v);
    lo = cvt_tf32(v - __uint_as_float(hi));
}
__device__ __forceinline__ void mma8(float* c, const uint32_t* a, const uint32_t* b) {
    asm volatile(
        "mma.sync.aligned.m16n8k8.row.col.f32.tf32.tf32.f32 "
        "{%0,%1,%2,%3}, {%4,%5,%6,%7}, {%8,%9}, {%0,%1,%2,%3};"
        : "+f"(c[0]), "+f"(c[1]), "+f"(c[2]), "+f"(c[3])
        : "r"(a[0]), "r"(a[1]), "r"(a[2]), "r"(a[3]), "r"(b[0]), "r"(b[1]));
}

// ---------------------------------------------------------------------------
// Fused projection via mma.sync tf32, 3-term hi/lo split (fp32-accurate).
// grid = BT/128 = 128 CTAs, block = 256 (8 warps as 4 m-warps x 2 n-warps).
// CTA tile: M=128, N=192 (q|k|v). Warp tile: 32 rows x 96 cols = 2x12 mma tiles.
// K staged 32 at a time, cp.async double-buffered, plain padded smem:
//   xs pad 36 -> A-fragment scalar LDS conflict-free (bank = 4*row+col = lane)
//   ws pad 68 -> ~2-way on B loads.
// ---------------------------------------------------------------------------
#define PJ_STAGE_FLOATS (128 * 36 + 3 * 32 * 68)   // 4608 + 6528 = 11136
#define PJ_SMEM_BYTES (2 * PJ_STAGE_FLOATS * 4)    // 89088

__device__ __forceinline__ void pj_stage_cp(float* stg, const float* __restrict__ x,
                                            const float* const* Ws,
                                            int row0, int k0, int tid)
{
    float* xs = stg;
    float* ws = stg + 128 * 36;
    #pragma unroll
    for (int t = 0; t < 4; t++) {
        int idx = tid + t * 256;
        int r = idx >> 3, cq = idx & 7;
        cp16(s2u(xs + r * 36 + cq * 4),
             &x[(size_t)(row0 + r) * EMB + k0 + cq * 4]);
    }
    #pragma unroll
    for (int t = 0; t < 6; t++) {
        int idx = tid + t * 256;
        int mat = idx >> 9, rem = idx & 511;
        int kk = rem >> 4, nq = rem & 15;
        cp16(s2u(ws + (mat * 32 + kk) * 68 + nq * 4),
             &Ws[mat][(size_t)(k0 + kk) * HD + nq * 4]);
    }
    asm volatile("cp.async.commit_group;" ::: "memory");
}

__global__ __launch_bounds__(256) void proj_mma_kernel(
    const float* __restrict__ x,
    const float* __restrict__ Wq,
    const float* __restrict__ Wk,
    const float* __restrict__ Wv)
{
    extern __shared__ float psm[];
    const int tid = threadIdx.x;
    const int lane = tid & 31;
    const int wid = tid >> 5;
    const int wr = wid >> 1;          // 0..3: rows 32*wr
    const int wc = wid & 1;           // 0..1: cols 96*wc
    const int row0 = blockIdx.x * 128;
    const int g = lane >> 2;          // groupID
    const int t4 = lane & 3;          // thread-in-group

    const float* Ws[3] = {Wq, Wk, Wv};

    float C[2][12][4];
    #pragma unroll
    for (int mt = 0; mt < 2; mt++)
        #pragma unroll
        for (int nt = 0; nt < 12; nt++)
            #pragma unroll
            for (int i = 0; i < 4; i++) C[mt][nt][i] = 0.0f;

    pj_stage_cp(psm, x, Ws, row0, 0, tid);
    pj_stage_cp(psm + PJ_STAGE_FLOATS, x, Ws, row0, 32, tid);

    for (int s = 0; s < 24; s++) {
        float* stg = psm + (s & 1) * PJ_STAGE_FLOATS;
        float* xs = stg;
        float* ws = stg + 128 * 36;

        if (s < 23) asm volatile("cp.async.wait_group 1;" ::: "memory");
        else        asm volatile("cp.async.wait_group 0;" ::: "memory");
        __syncthreads();

        #pragma unroll
        for (int ks = 0; ks < 4; ks++) {
            // A fragments (hi/lo) for the 2 m-tiles
            uint32_t ahi[2][4], alo[2][4];
            #pragma unroll
            for (int mt = 0; mt < 2; mt++) {
                int rb = wr * 32 + mt * 16 + g;
                int cb = ks * 8 + t4;
                hilo(xs[rb * 36 + cb],           ahi[mt][0], alo[mt][0]);
                hilo(xs[(rb + 8) * 36 + cb],     ahi[mt][1], alo[mt][1]);
                hilo(xs[rb * 36 + cb + 4],       ahi[mt][2], alo[mt][2]);
                hilo(xs[(rb + 8) * 36 + cb + 4], ahi[mt][3], alo[mt][3]);
            }
            #pragma unroll
            for (int nt = 0; nt < 12; nt++) {
                int gn = wc * 96 + nt * 8;
                int mat = gn >> 6;
                int ncol = (gn & 63) + g;
                const float* wb = ws + (mat * 32 + ks * 8) * 68 + ncol;
                uint32_t bhi[2], blo[2];
                hilo(wb[t4 * 68],       bhi[0], blo[0]);
                hilo(wb[(t4 + 4) * 68], bhi[1], blo[1]);
                #pragma unroll
                for (int mt = 0; mt < 2; mt++) {
                    mma8(C[mt][nt], ahi[mt], bhi);
                    mma8(C[mt][nt], ahi[mt], blo);
                    mma8(C[mt][nt], alo[mt], bhi);
                }
            }
        }
        __syncthreads();

        if (s + 2 < 24)
            pj_stage_cp(psm + (s & 1) * PJ_STAGE_FLOATS, x, Ws, row0, (s + 2) * 32, tid);
    }

    // Epilogue: write C fragments to g_q / g_k / g_v
    float* outs[3] = {g_q, g_k, g_v};
    #pragma unroll
    for (int mt = 0; mt < 2; mt++) {
        #pragma unroll
        for (int nt = 0; nt < 12; nt++) {
            int gn = wc * 96 + nt * 8;
            int mat = gn >> 6;
            int col = (gn & 63) + t4 * 2;
            int row = row0 + wr * 32 + mt * 16 + g;
            float* op = outs[mat];
            *reinterpret_cast<float2*>(&op[(size_t)row * HD + col]) =
                make_float2(C[mt][nt][0], C[mt][nt][1]);
            *reinterpret_cast<float2*>(&op[(size_t)(row + 8) * HD + col]) =
                make_float2(C[mt][nt][2], C[mt][nt][3]);
        }
    }
}

// ---------------------------------------------------------------------------
// Flash attention (causal), fp32 via f32x2, split-K for qi>=32. (unchanged)
// ---------------------------------------------------------------------------
#define ATTN_SMEM_FLOATS (4096 + 8192 + 8192 + 64 * 68)
#define ATTN_SMEM_BYTES (ATTN_SMEM_FLOATS * 4)

__device__ __forceinline__ void tile_cp(float* Kb, float* Vb,
                                        const float* Kg, const float* Vg, int tid)
{
    #pragma unroll
    for (int t = 0; t < 4; t++) {
        int c = tid + t * 256;
        int row = c >> 4, g = c & 15;
        int d = (g ^ (row >> 2)) << 2;
        cp16(s2u(Kb + row * 64 + d), Kg + row * 64 + g * 4);
    }
    #pragma unroll
    for (int t = 0; t < 4; t++) {
        int c = tid + t * 256;
        int row = c >> 4, g = c & 15;
        int d = (g ^ (row >> 2)) << 2;
        cp16(s2u(Vb + row * 64 + d), Vg + row * 64 + g * 4);
    }
    asm volatile("cp.async.commit_group;" ::: "memory");
}

__global__ __launch_bounds__(256, 2) void attn_kernel(float* __restrict__ out)
{
    extern __shared__ float sm[];
    float* Qs = sm;              // [64][64]
    float* Kd = sm + 4096;       // 2 x [64][64] swizzled
    float* Vd = sm + 12288;      // 2 x [64][64] swizzled
    float* Ps = sm + 20480;      // [64][68]

    const int tid = threadIdx.x;
    const int tx = tid & 15, ty = tid >> 4;
    const int b = blockIdx.y;
    const int i0 = blockIdx.x;

    int qi, k0t, k1t, part;
    bool partial;
    if (i0 < 64) {
        qi = 63 - (i0 >> 1);
        part = i0 & 1;
        int hs = (qi + 1) >> 1;
        if (part == 0) { k0t = 0;  k1t = hs - 1; }
        else           { k0t = hs; k1t = qi; }
        partial = true;
    } else {
        qi = 95 - i0; part = 0; k0t = 0; k1t = qi; partial = false;
    }

    const float* Kbase = g_k + (size_t)b * SEQT * HD;
    const float* Vbase = g_v + (size_t)b * SEQT * HD;

    tile_cp(Kd + (k0t & 1) * 4096, Vd + (k0t & 1) * 4096,
            Kbase + (size_t)k0t * 64 * HD, Vbase + (size_t)k0t * 64 * HD, tid);
    if (k0t + 1 <= k1t)
        tile_cp(Kd + ((k0t + 1) & 1) * 4096, Vd + ((k0t + 1) & 1) * 4096,
                Kbase + (size_t)(k0t + 1) * 64 * HD, Vbase + (size_t)(k0t + 1) * 64 * HD, tid);

    const float* Qg = g_q + ((size_t)b * SEQT + qi * 64) * HD;
    for (int i = tid; i < 1024; i += 256) {
        float4 v = reinterpret_cast<const float4*>(Qg)[i];
        v.x *= 0.125f; v.y *= 0.125f; v.z *= 0.125f; v.w *= 0.125f;
        reinterpret_cast<float4*>(Qs)[i] = v;
    }

    float rm[4], rs[4];
    ull o2[4][2];
    #pragma unroll
    for (int i = 0; i < 4; i++) {
        rm[i] = -CUDART_INF_F; rs[i] = 0.0f;
        o2[i][0] = 0ull; o2[i][1] = 0ull;
    }

    for (int kt = k0t; kt <= k1t; kt++) {
        float* Kb = Kd + (kt & 1) * 4096;
        float* Vb = Vd + (kt & 1) * 4096;

        if (kt < k1t) asm volatile("cp.async.wait_group 1;" ::: "memory");
        else          asm volatile("cp.async.wait_group 0;" ::: "memory");
        __syncthreads();

        ull s2[4][4];
        #pragma unroll
        for (int i = 0; i < 4; i++)
            #pragma unroll
            for (int j = 0; j < 4; j++) s2[i][j] = 0ull;

        #pragma unroll 4
        for (int dg = 0; dg < 16; dg++) {
            ulonglong2 q[4];
            #pragma unroll
            for (int i = 0; i < 4; i++)
                q[i] = *reinterpret_cast<ulonglong2*>(&Qs[(ty * 4 + i) * 64 + dg * 4]);
            #pragma unroll
            for (int j = 0; j < 4; j++) {
                ulonglong2 k = *reinterpret_cast<ulonglong2*>(
                    &Kb[(tx * 4 + j) * 64 + ((dg ^ tx) << 2)]);
                #pragma unroll
                for (int i = 0; i < 4; i++) {
                    ffma2(s2[i][j], q[i].x, k.x);
                    ffma2(s2[i][j], q[i].y, k.y);
                }
            }
        }

        float s[4][4];
        #pragma unroll
        for (int i = 0; i < 4; i++)
            #pragma unroll
            for (int j = 0; j < 4; j++) s[i][j] = hadd2(s2[i][j]);

        if (kt == qi) {
            #pragma unroll
            for (int i = 0; i < 4; i++)
                #pragma unroll
                for (int j = 0; j < 4; j++)
                    if (tx * 4 + j > ty * 4 + i) s[i][j] = -CUDART_INF_F;
        }

        #pragma unroll
        for (int i = 0; i < 4; i++) {
            float m = fmaxf(fmaxf(s[i][0], s[i][1]), fmaxf(s[i][2], s[i][3]));
            m = fmaxf(m, __shfl_xor_sync(0xffffffffu, m, 1, 16));
            m = fmaxf(m, __shfl_xor_sync(0xffffffffu, m, 2, 16));
            m = fmaxf(m, __shfl_xor_sync(0xffffffffu, m, 4, 16));
            m = fmaxf(m, __shfl_xor_sync(0xffffffffu, m, 8, 16));
            float nm = fmaxf(rm[i], m);
            float alpha = __expf(rm[i] - nm);
            rm[i] = nm;

            float p0 = __expf(s[i][0] - nm);
            float p1 = __expf(s[i][1] - nm);
            float p2 = __expf(s[i][2] - nm);
            float p3 = __expf(s[i][3] - nm);
            float ts = (p0 + p1) + (p2 + p3);
            ts += __shfl_xor_sync(0xffffffffu, ts, 1, 16);
            ts += __shfl_xor_sync(0xffffffffu, ts, 2, 16);
            ts += __shfl_xor_sync(0xffffffffu, ts, 4, 16);
            ts += __shfl_xor_sync(0xffffffffu, ts, 8, 16);
            rs[i] = rs[i] * alpha + ts;

            ull ad = dup2(alpha);
            fmul2(o2[i][0], o2[i][0], ad);
            fmul2(o2[i][1], o2[i][1], ad);

            *reinterpret_cast<float4*>(&Ps[(ty * 4 + i) * 68 + tx * 4]) =
                make_float4(p0, p1, p2, p3);
        }
        __syncthreads();

        #pragma unroll 2
        for (int ng = 0; ng < 16; ng++) {
            float4 p4[4];
            #pragma unroll
            for (int i = 0; i < 4; i++)
                p4[i] = *reinterpret_cast<float4*>(&Ps[(ty * 4 + i) * 68 + ng * 4]);
            #pragma unroll
            for (int l = 0; l < 4; l++) {
                int n = ng * 4 + l;
                ulonglong2 v = *reinterpret_cast<ulonglong2*>(
                    &Vb[n * 64 + ((tx ^ (n >> 2)) << 2)]);
                #pragma unroll
                for (int i = 0; i < 4; i++) {
                    ull pd = dup2(reinterpret_cast<float*>(&p4[i])[l]);
                    ffma2(o2[i][0], pd, v.x);
                    ffma2(o2[i][1], pd, v.y);
                }
            }
        }
        __syncthreads();

        if (kt + 2 <= k1t)
            tile_cp(Kd + (kt & 1) * 4096, Vd + (kt & 1) * 4096,
                    Kbase + (size_t)(kt + 2) * 64 * HD,
                    Vbase + (size_t)(kt + 2) * 64 * HD, tid);
    }

    if (!partial) {
        #pragma unroll
        for (int i = 0; i < 4; i++) {
            float inv = 1.0f / rs[i];
            float c0, c1, c2, c3;
            unpack2(o2[i][0], c0, c1);
            unpack2(o2[i][1], c2, c3);
            size_t row = (size_t)b * SEQT + qi * 64 + ty * 4 + i;
            *reinterpret_cast<float4*>(&out[row * HD + tx * 4]) =
                make_float4(c0 * inv, c1 * inv, c2 * inv, c3 * inv);
        }
    } else {
        #pragma unroll
        for (int i = 0; i < 4; i++) {
            int gr = b * SEQT + qi * 64 + ty * 4 + i;
            float c0, c1, c2, c3;
            unpack2(o2[i][0], c0, c1);
            unpack2(o2[i][1], c2, c3);
            *reinterpret_cast<float4*>(&g_po[part][(size_t)gr * HD + tx * 4]) =
                make_float4(c0, c1, c2, c3);
            if (tx == 0) { g_pm[part][gr] = rm[i]; g_pl[part][gr] = rs[i]; }
        }
    }
}

// ---------------------------------------------------------------------------
// Combine split-K partials (rows with qi >= 32). (unchanged)
// ---------------------------------------------------------------------------
__global__ __launch_bounds__(256) void combine_kernel(float* __restrict__ out)
{
    int idx = blockIdx.x * 256 + threadIdx.x;
    int hr = idx >> 4;
    int c4 = (idx & 15) << 2;
    int b = hr >> 11;
    int r = 2048 + (hr & 2047);
    int gr = b * SEQT + r;

    float m0 = g_pm[0][gr], m1 = g_pm[1][gr];
    float M = fmaxf(m0, m1);
    float e0 = __expf(m0 - M), e1 = __expf(m1 - M);
    float den = e0 * g_pl[0][gr] + e1 * g_pl[1][gr];
    float inv = 1.0f / den;

    float4 a = *reinterpret_cast<float4*>(&g_po[0][(size_t)gr * HD + c4]);
    float4 c = *reinterpret_cast<float4*>(&g_po[1][(size_t)gr * HD + c4]);
    float4 o;
    o.x = (e0 * a.x + e1 * c.x) * inv;
    o.y = (e0 * a.y + e1 * c.y) * inv;
    o.z = (e0 * a.z + e1 * c.z) * inv;
    o.w = (e0 * a.w + e1 * c.w) * inv;
    *reinterpret_cast<float4*>(&out[(size_t)gr * HD + c4]) = o;
}

extern "C" void kernel_launch(void* const* d_in, const int* in_sizes, int n_in,
                              void* d_out, int out_size) {
    (void)in_sizes; (void)n_in; (void)out_size;
    const float* x  = (const float*)d_in[0];
    const float* Wk = (const float*)d_in[1];
    const float* Wq = (const float*)d_in[2];
    const float* Wv = (const float*)d_in[3];
    float* out = (float*)d_out;

    cudaFuncSetAttribute(proj_mma_kernel,
                         cudaFuncAttributeMaxDynamicSharedMemorySize,
                         PJ_SMEM_BYTES);
    proj_mma_kernel<<<BT / 128, 256, PJ_SMEM_BYTES>>>(x, Wq, Wk, Wv);

    cudaFuncSetAttribute(attn_kernel,
                         cudaFuncAttributeMaxDynamicSharedMemorySize,
                         ATTN_SMEM_BYTES);
    dim3 ag(96, BATCH);
    attn_kernel<<<ag, 256, ATTN_SMEM_BYTES>>>(out);

    combine_kernel<<<512, 256>>>(out);
}

// round 6
// speedup vs baseline: 1.7311x; 1.1159x over previous
#include <cuda_runtime.h>
#include <math_constants.h>
#include <cstdint>

#define BATCH 4
#define SEQT 4096
#define EMB 768
#define HD 64
#define BT (BATCH * SEQT)

typedef unsigned long long ull;

// Scratch (device globals: no allocation allowed)
__device__ float g_q[BT * HD];
__device__ float g_k[BT * HD];
__device__ float g_v[BT * HD];
__device__ float g_po[2][BT * HD];  // split-K partial numerators
__device__ float g_pm[2][BT];       // split-K partial row max
__device__ float g_pl[2][BT];       // split-K partial row sum

__device__ __forceinline__ uint32_t s2u(const void* p) {
    return (uint32_t)__cvta_generic_to_shared(p);
}
__device__ __forceinline__ void cp16(uint32_t dst, const void* src) {
    asm volatile("cp.async.ca.shared.global [%0], [%1], 16;" :: "r"(dst), "l"(src));
}

// ---- mma.sync tf32 helpers (sm_80+ path; no 'a' features) ----
__device__ __forceinline__ uint32_t cvt_tf32(float f) {
    uint32_t r; asm("cvt.rna.tf32.f32 %0, %1;" : "=r"(r) : "f"(f)); return r;
}
__device__ __forceinline__ void hilo(float v, uint32_t& hi, uint32_t& lo) {
    hi = cvt_tf32(v);
    lo = cvt_tf32(v - __uint_as_float(hi));
}
__device__ __forceinline__ void mma8(float* c, const uint32_t* a, const uint32_t* b) {
    asm volatile(
        "mma.sync.aligned.m16n8k8.row.col.f32.tf32.tf32.f32 "
        "{%0,%1,%2,%3}, {%4,%5,%6,%7}, {%8,%9}, {%0,%1,%2,%3};"
        : "+f"(c[0]), "+f"(c[1]), "+f"(c[2]), "+f"(c[3])
        : "r"(a[0]), "r"(a[1]), "r"(a[2]), "r"(a[3]), "r"(b[0]), "r"(b[1]));
}

// ---------------------------------------------------------------------------
// Fused projection via mma.sync tf32, 3-term hi/lo split. (unchanged from R5)
// ---------------------------------------------------------------------------
#define PJ_STAGE_FLOATS (128 * 36 + 3 * 32 * 68)
#define PJ_SMEM_BYTES (2 * PJ_STAGE_FLOATS * 4)

__device__ __forceinline__ void pj_stage_cp(float* stg, const float* __restrict__ x,
                                            const float* const* Ws,
                                            int row0, int k0, int tid)
{
    float* xs = stg;
    float* ws = stg + 128 * 36;
    #pragma unroll
    for (int t = 0; t < 4; t++) {
        int idx = tid + t * 256;
        int r = idx >> 3, cq = idx & 7;
        cp16(s2u(xs + r * 36 + cq * 4),
             &x[(size_t)(row0 + r) * EMB + k0 + cq * 4]);
    }
    #pragma unroll
    for (int t = 0; t < 6; t++) {
        int idx = tid + t * 256;
        int mat = idx >> 9, rem = idx & 511;
        int kk = rem >> 4, nq = rem & 15;
        cp16(s2u(ws + (mat * 32 + kk) * 68 + nq * 4),
             &Ws[mat][(size_t)(k0 + kk) * HD + nq * 4]);
    }
    asm volatile("cp.async.commit_group;" ::: "memory");
}

__global__ __launch_bounds__(256) void proj_mma_kernel(
    const float* __restrict__ x,
    const float* __restrict__ Wq,
    const float* __restrict__ Wk,
    const float* __restrict__ Wv)
{
    extern __shared__ float psm[];
    const int tid = threadIdx.x;
    const int lane = tid & 31;
    const int wid = tid >> 5;
    const int wr = wid >> 1;
    const int wc = wid & 1;
    const int row0 = blockIdx.x * 128;
    const int g = lane >> 2;
    const int t4 = lane & 3;

    const float* Ws[3] = {Wq, Wk, Wv};

    float C[2][12][4];
    #pragma unroll
    for (int mt = 0; mt < 2; mt++)
        #pragma unroll
        for (int nt = 0; nt < 12; nt++)
            #pragma unroll
            for (int i = 0; i < 4; i++) C[mt][nt][i] = 0.0f;

    pj_stage_cp(psm, x, Ws, row0, 0, tid);
    pj_stage_cp(psm + PJ_STAGE_FLOATS, x, Ws, row0, 32, tid);

    for (int s = 0; s < 24; s++) {
        float* stg = psm + (s & 1) * PJ_STAGE_FLOATS;
        float* xs = stg;
        float* ws = stg + 128 * 36;

        if (s < 23) asm volatile("cp.async.wait_group 1;" ::: "memory");
        else        asm volatile("cp.async.wait_group 0;" ::: "memory");
        __syncthreads();

        #pragma unroll
        for (int ks = 0; ks < 4; ks++) {
            uint32_t ahi[2][4], alo[2][4];
            #pragma unroll
            for (int mt = 0; mt < 2; mt++) {
                int rb = wr * 32 + mt * 16 + g;
                int cb = ks * 8 + t4;
                hilo(xs[rb * 36 + cb],           ahi[mt][0], alo[mt][0]);
                hilo(xs[(rb + 8) * 36 + cb],     ahi[mt][1], alo[mt][1]);
                hilo(xs[rb * 36 + cb + 4],       ahi[mt][2], alo[mt][2]);
                hilo(xs[(rb + 8) * 36 + cb + 4], ahi[mt][3], alo[mt][3]);
            }
            #pragma unroll
            for (int nt = 0; nt < 12; nt++) {
                int gn = wc * 96 + nt * 8;
                int mat = gn >> 6;
                int ncol = (gn & 63) + g;
                const float* wb = ws + (mat * 32 + ks * 8) * 68 + ncol;
                uint32_t bhi[2], blo[2];
                hilo(wb[t4 * 68],       bhi[0], blo[0]);
                hilo(wb[(t4 + 4) * 68], bhi[1], blo[1]);
                #pragma unroll
                for (int mt = 0; mt < 2; mt++) {
                    mma8(C[mt][nt], ahi[mt], bhi);
                    mma8(C[mt][nt], ahi[mt], blo);
                    mma8(C[mt][nt], alo[mt], bhi);
                }
            }
        }
        __syncthreads();

        if (s + 2 < 24)
            pj_stage_cp(psm + (s & 1) * PJ_STAGE_FLOATS, x, Ws, row0, (s + 2) * 32, tid);
    }

    float* outs[3] = {g_q, g_k, g_v};
    #pragma unroll
    for (int mt = 0; mt < 2; mt++) {
        #pragma unroll
        for (int nt = 0; nt < 12; nt++) {
            int gn = wc * 96 + nt * 8;
            int mat = gn >> 6;
            int col = (gn & 63) + t4 * 2;
            int row = row0 + wr * 32 + mt * 16 + g;
            float* op = outs[mat];
            *reinterpret_cast<float2*>(&op[(size_t)row * HD + col]) =
                make_float2(C[mt][nt][0], C[mt][nt][1]);
            *reinterpret_cast<float2*>(&op[(size_t)(row + 8) * HD + col]) =
                make_float2(C[mt][nt][2], C[mt][nt][3]);
        }
    }
}

// ---------------------------------------------------------------------------
// Flash attention (causal) via mma.sync tf32, 3-term hi/lo on both GEMMs.
// Same split-K schedule as before: grid (96, B); i0<64 -> split halves of
// qi=63-(i0>>1); i0>=64 -> unsplit qi=95-i0. 256 threads = 8 warps:
// mw=wid>>1 (16 S-rows), nw=wid&1 (32 S-cols / 32 O-cols).
// smem pads: Q/K 68, V 72, P 76 -> conflict-free fragment LDS.
// ---------------------------------------------------------------------------
#define AQ 68
#define AK 68
#define AV 72
#define AP 76
#define OFF_Q 0
#define OFF_K 4352
#define OFF_V 13056
#define OFF_P 22272
#define OFF_WMX 27136
#define OFF_WSM 27264
#define ATTN_SMEM_FLOATS 27392
#define ATTN_SMEM_BYTES (ATTN_SMEM_FLOATS * 4)

__device__ __forceinline__ void tile_cp2(float* Kb, float* Vb,
                                         const float* Kg, const float* Vg, int tid)
{
    #pragma unroll
    for (int t = 0; t < 4; t++) {
        int idx = tid + t * 256;
        int row = idx >> 4, q = idx & 15;
        cp16(s2u(Kb + row * AK + q * 4), Kg + row * 64 + q * 4);
    }
    #pragma unroll
    for (int t = 0; t < 4; t++) {
        int idx = tid + t * 256;
        int row = idx >> 4, q = idx & 15;
        cp16(s2u(Vb + row * AV + q * 4), Vg + row * 64 + q * 4);
    }
    asm volatile("cp.async.commit_group;" ::: "memory");
}

__global__ __launch_bounds__(256, 2) void attn_mma_kernel(float* __restrict__ out)
{
    extern __shared__ float sm[];
    float* Qs  = sm + OFF_Q;    // [64][68]
    float* Kd  = sm + OFF_K;    // 2 x [64][68]
    float* Vd  = sm + OFF_V;    // 2 x [64][72]
    float* Ps  = sm + OFF_P;    // [64][76]
    float* Wmx = sm + OFF_WMX;  // [2][64]
    float* Wsm = sm + OFF_WSM;  // [2][64]

    const int tid = threadIdx.x;
    const int lane = tid & 31;
    const int wid = tid >> 5;
    const int mw = wid >> 1;
    const int nw = wid & 1;
    const int g = lane >> 2;
    const int t4 = lane & 3;
    const int b = blockIdx.y;
    const int i0 = blockIdx.x;

    int qi, k0t, k1t, part;
    bool partial;
    if (i0 < 64) {
        qi = 63 - (i0 >> 1);
        part = i0 & 1;
        int hs = (qi + 1) >> 1;
        if (part == 0) { k0t = 0;  k1t = hs - 1; }
        else           { k0t = hs; k1t = qi; }
        partial = true;
    } else {
        qi = 95 - i0; part = 0; k0t = 0; k1t = qi; partial = false;
    }

    const float* Kbase = g_k + (size_t)b * SEQT * HD;
    const float* Vbase = g_v + (size_t)b * SEQT * HD;

    tile_cp2(Kd + (k0t & 1) * 4352, Vd + (k0t & 1) * 4608,
             Kbase + (size_t)k0t * 64 * HD, Vbase + (size_t)k0t * 64 * HD, tid);
    if (k0t + 1 <= k1t)
        tile_cp2(Kd + ((k0t + 1) & 1) * 4352, Vd + ((k0t + 1) & 1) * 4608,
                 Kbase + (size_t)(k0t + 1) * 64 * HD,
                 Vbase + (size_t)(k0t + 1) * 64 * HD, tid);

    // Q tile load (pre-scaled by 1/sqrt(HD))
    const float* Qg = g_q + ((size_t)b * SEQT + qi * 64) * HD;
    #pragma unroll
    for (int t = 0; t < 4; t++) {
        int idx = tid + t * 256;
        int row = idx >> 4, q = idx & 15;
        float4 v = *reinterpret_cast<const float4*>(Qg + row * 64 + q * 4);
        v.x *= 0.125f; v.y *= 0.125f; v.z *= 0.125f; v.w *= 0.125f;
        *reinterpret_cast<float4*>(&Qs[row * AQ + q * 4]) = v;
    }

    const int r0 = 16 * mw + g;       // local S/O row (lane's first row)
    float rm0 = -CUDART_INF_F, rm1 = -CUDART_INF_F;
    float rs0 = 0.0f, rs1 = 0.0f;
    float O[4][4];
    #pragma unroll
    for (int nt = 0; nt < 4; nt++)
        #pragma unroll
        for (int i = 0; i < 4; i++) O[nt][i] = 0.0f;

    for (int kt = k0t; kt <= k1t; kt++) {
        float* Kb = Kd + (kt & 1) * 4352;
        float* Vb = Vd + (kt & 1) * 4608;

        if (kt < k1t) asm volatile("cp.async.wait_group 1;" ::: "memory");
        else          asm volatile("cp.async.wait_group 0;" ::: "memory");
        __syncthreads();

        // ---- S = Q K^T (3-term tf32) ----
        float S[4][4];
        #pragma unroll
        for (int nt = 0; nt < 4; nt++)
            #pragma unroll
            for (int i = 0; i < 4; i++) S[nt][i] = 0.0f;

        #pragma unroll
        for (int ks = 0; ks < 8; ks++) {
            uint32_t ahi[4], alo[4];
            int cb = ks * 8 + t4;
            hilo(Qs[r0 * AQ + cb],           ahi[0], alo[0]);
            hilo(Qs[(r0 + 8) * AQ + cb],     ahi[1], alo[1]);
            hilo(Qs[r0 * AQ + cb + 4],       ahi[2], alo[2]);
            hilo(Qs[(r0 + 8) * AQ + cb + 4], ahi[3], alo[3]);
            #pragma unroll
            for (int nt = 0; nt < 4; nt++) {
                int tok = 32 * nw + 8 * nt + g;
                uint32_t bhi[2], blo[2];
                hilo(Kb[tok * AK + cb],     bhi[0], blo[0]);
                hilo(Kb[tok * AK + cb + 4], bhi[1], blo[1]);
                mma8(S[nt], ahi, bhi);
                mma8(S[nt], ahi, blo);
                mma8(S[nt], alo, bhi);
            }
        }

        // ---- causal mask on diagonal tile ----
        if (kt == qi) {
            #pragma unroll
            for (int nt = 0; nt < 4; nt++) {
                int colb = 32 * nw + 8 * nt + 2 * t4;
                if (colb     > r0)     S[nt][0] = -CUDART_INF_F;
                if (colb + 1 > r0)     S[nt][1] = -CUDART_INF_F;
                if (colb     > r0 + 8) S[nt][2] = -CUDART_INF_F;
                if (colb + 1 > r0 + 8) S[nt][3] = -CUDART_INF_F;
            }
        }

        // ---- partial row max over this warp's 32 cols ----
        float m0 = fmaxf(fmaxf(S[0][0], S[0][1]), fmaxf(S[1][0], S[1][1]));
        m0 = fmaxf(m0, fmaxf(fmaxf(S[2][0], S[2][1]), fmaxf(S[3][0], S[3][1])));
        float m1 = fmaxf(fmaxf(S[0][2], S[0][3]), fmaxf(S[1][2], S[1][3]));
        m1 = fmaxf(m1, fmaxf(fmaxf(S[2][2], S[2][3]), fmaxf(S[3][2], S[3][3])));
        m0 = fmaxf(m0, __shfl_xor_sync(0xffffffffu, m0, 1));
        m0 = fmaxf(m0, __shfl_xor_sync(0xffffffffu, m0, 2));
        m1 = fmaxf(m1, __shfl_xor_sync(0xffffffffu, m1, 1));
        m1 = fmaxf(m1, __shfl_xor_sync(0xffffffffu, m1, 2));
        if (t4 == 0) {
            Wmx[nw * 64 + r0] = m0;
            Wmx[nw * 64 + r0 + 8] = m1;
        }
        __syncthreads();

        float nm0 = fmaxf(rm0, fmaxf(Wmx[r0], Wmx[64 + r0]));
        float nm1 = fmaxf(rm1, fmaxf(Wmx[r0 + 8], Wmx[64 + r0 + 8]));
        float alpha0 = __expf(rm0 - nm0);
        float alpha1 = __expf(rm1 - nm1);
        rm0 = nm0; rm1 = nm1;

        // ---- p = exp(s - nm), store to Ps, partial sums ----
        float sum0 = 0.0f, sum1 = 0.0f;
        #pragma unroll
        for (int nt = 0; nt < 4; nt++) {
            float p00 = __expf(S[nt][0] - nm0);
            float p01 = __expf(S[nt][1] - nm0);
            float p10 = __expf(S[nt][2] - nm1);
            float p11 = __expf(S[nt][3] - nm1);
            sum0 += p00 + p01;
            sum1 += p10 + p11;
            int col = 32 * nw + 8 * nt + 2 * t4;
            *reinterpret_cast<float2*>(&Ps[r0 * AP + col]) = make_float2(p00, p01);
            *reinterpret_cast<float2*>(&Ps[(r0 + 8) * AP + col]) = make_float2(p10, p11);
        }
        sum0 += __shfl_xor_sync(0xffffffffu, sum0, 1);
        sum0 += __shfl_xor_sync(0xffffffffu, sum0, 2);
        sum1 += __shfl_xor_sync(0xffffffffu, sum1, 1);
        sum1 += __shfl_xor_sync(0xffffffffu, sum1, 2);
        if (t4 == 0) {
            Wsm[nw * 64 + r0] = sum0;
            Wsm[nw * 64 + r0 + 8] = sum1;
        }
        __syncthreads();

        rs0 = rs0 * alpha0 + Wsm[r0] + Wsm[64 + r0];
        rs1 = rs1 * alpha1 + Wsm[r0 + 8] + Wsm[64 + r0 + 8];

        #pragma unroll
        for (int nt = 0; nt < 4; nt++) {
            O[nt][0] *= alpha0; O[nt][1] *= alpha0;
            O[nt][2] *= alpha1; O[nt][3] *= alpha1;
        }

        // ---- O += P @ V (3-term tf32) ----
        #pragma unroll
        for (int ks = 0; ks < 8; ks++) {
            uint32_t ahi[4], alo[4];
            int kk = ks * 8 + t4;
            hilo(Ps[r0 * AP + kk],           ahi[0], alo[0]);
            hilo(Ps[(r0 + 8) * AP + kk],     ahi[1], alo[1]);
            hilo(Ps[r0 * AP + kk + 4],       ahi[2], alo[2]);
            hilo(Ps[(r0 + 8) * AP + kk + 4], ahi[3], alo[3]);
            #pragma unroll
            for (int nt = 0; nt < 4; nt++) {
                int dcol = 32 * nw + 8 * nt + g;
                uint32_t bhi[2], blo[2];
                hilo(Vb[kk * AV + dcol],       bhi[0], blo[0]);
                hilo(Vb[(kk + 4) * AV + dcol], bhi[1], blo[1]);
                mma8(O[nt], ahi, bhi);
                mma8(O[nt], ahi, blo);
                mma8(O[nt], alo, bhi);
            }
        }
        __syncthreads();

        if (kt + 2 <= k1t)
            tile_cp2(Kd + (kt & 1) * 4352, Vd + (kt & 1) * 4608,
                     Kbase + (size_t)(kt + 2) * 64 * HD,
                     Vbase + (size_t)(kt + 2) * 64 * HD, tid);
    }

    // ---- epilogue ----
    if (!partial) {
        float inv0 = 1.0f / rs0, inv1 = 1.0f / rs1;
        #pragma unroll
        for (int nt = 0; nt < 4; nt++) {
            int col = 32 * nw + 8 * nt + 2 * t4;
            size_t row = (size_t)b * SEQT + qi * 64 + r0;
            *reinterpret_cast<float2*>(&out[row * HD + col]) =
                make_float2(O[nt][0] * inv0, O[nt][1] * inv0);
            *reinterpret_cast<float2*>(&out[(row + 8) * HD + col]) =
                make_float2(O[nt][2] * inv1, O[nt][3] * inv1);
        }
    } else {
        int gr = b * SEQT + qi * 64 + r0;
        #pragma unroll
        for (int nt = 0; nt < 4; nt++) {
            int col = 32 * nw + 8 * nt + 2 * t4;
            *reinterpret_cast<float2*>(&g_po[part][(size_t)gr * HD + col]) =
                make_float2(O[nt][0], O[nt][1]);
            *reinterpret_cast<float2*>(&g_po[part][(size_t)(gr + 8) * HD + col]) =
                make_float2(O[nt][2], O[nt][3]);
        }
        if (nw == 0 && t4 == 0) {
            g_pm[part][gr] = rm0;     g_pl[part][gr] = rs0;
            g_pm[part][gr + 8] = rm1; g_pl[part][gr + 8] = rs1;
        }
    }
}

// ---------------------------------------------------------------------------
// Combine split-K partials (rows with qi >= 32). (unchanged)
// ---------------------------------------------------------------------------
__global__ __launch_bounds__(256) void combine_kernel(float* __restrict__ out)
{
    int idx = blockIdx.x * 256 + threadIdx.x;
    int hr = idx >> 4;
    int c4 = (idx & 15) << 2;
    int b = hr >> 11;
    int r = 2048 + (hr & 2047);
    int gr = b * SEQT + r;

    float m0 = g_pm[0][gr], m1 = g_pm[1][gr];
    float M = fmaxf(m0, m1);
    float e0 = __expf(m0 - M), e1 = __expf(m1 - M);
    float den = e0 * g_pl[0][gr] + e1 * g_pl[1][gr];
    float inv = 1.0f / den;

    float4 a = *reinterpret_cast<float4*>(&g_po[0][(size_t)gr * HD + c4]);
    float4 c = *reinterpret_cast<float4*>(&g_po[1][(size_t)gr * HD + c4]);
    float4 o;
    o.x = (e0 * a.x + e1 * c.x) * inv;
    o.y = (e0 * a.y + e1 * c.y) * inv;
    o.z = (e0 * a.z + e1 * c.z) * inv;
    o.w = (e0 * a.w + e1 * c.w) * inv;
    *reinterpret_cast<float4*>(&out[(size_t)gr * HD + c4]) = o;
}

extern "C" void kernel_launch(void* const* d_in, const int* in_sizes, int n_in,
                              void* d_out, int out_size) {
    (void)in_sizes; (void)n_in; (void)out_size;
    const float* x  = (const float*)d_in[0];
    const float* Wk = (const float*)d_in[1];
    const float* Wq = (const float*)d_in[2];
    const float* Wv = (const float*)d_in[3];
    float* out = (float*)d_out;

    cudaFuncSetAttribute(proj_mma_kernel,
                         cudaFuncAttributeMaxDynamicSharedMemorySize,
                         PJ_SMEM_BYTES);
    proj_mma_kernel<<<BT / 128, 256, PJ_SMEM_BYTES>>>(x, Wq, Wk, Wv);

    cudaFuncSetAttribute(attn_mma_kernel,
                         cudaFuncAttributeMaxDynamicSharedMemorySize,
                         ATTN_SMEM_BYTES);
    dim3 ag(96, BATCH);
    attn_mma_kernel<<<ag, 256, ATTN_SMEM_BYTES>>>(out);

    combine_kernel<<<512, 256>>>(out);
}

// round 7
// speedup vs baseline: 2.6864x; 1.5519x over previous
#include <cuda_runtime.h>
#include <cuda_bf16.h>
#include <math_constants.h>
#include <cstdint>

#define BATCH 4
#define SEQT 4096
#define EMB 768
#define HD 64
#define BT (BATCH * SEQT)

typedef unsigned long long ull;

// Scratch (device globals: no allocation allowed)
// q/k planes: row-major [token][d], bf16 hi/lo. v planes: TRANSPOSED
// [(b*HD + d)][token], bf16 hi/lo (so PV B-fragments load tok-pairs directly).
__device__ __nv_bfloat16 g_qh[BT * HD], g_ql[BT * HD];
__device__ __nv_bfloat16 g_kh[BT * HD], g_kl[BT * HD];
__device__ __nv_bfloat16 g_vh[BT * HD], g_vl[BT * HD];
__device__ float g_po[2][BT * HD];  // split-K partial numerators
__device__ float g_pm[2][BT];       // split-K partial row max
__device__ float g_pl[2][BT];       // split-K partial row sum

__device__ __forceinline__ uint32_t s2u(const void* p) {
    return (uint32_t)__cvta_generic_to_shared(p);
}
__device__ __forceinline__ void cp16(uint32_t dst, const void* src) {
    asm volatile("cp.async.ca.shared.global [%0], [%1], 16;" :: "r"(dst), "l"(src));
}

// ---- tf32 helpers (projection mainloop, unchanged from R5/R6) ----
__device__ __forceinline__ uint32_t cvt_tf32(float f) {
    uint32_t r; asm("cvt.rna.tf32.f32 %0, %1;" : "=r"(r) : "f"(f)); return r;
}
__device__ __forceinline__ void hilo(float v, uint32_t& hi, uint32_t& lo) {
    hi = cvt_tf32(v);
    lo = cvt_tf32(v - __uint_as_float(hi));
}
__device__ __forceinline__ void mma8(float* c, const uint32_t* a, const uint32_t* b) {
    asm volatile(
        "mma.sync.aligned.m16n8k8.row.col.f32.tf32.tf32.f32 "
        "{%0,%1,%2,%3}, {%4,%5,%6,%7}, {%8,%9}, {%0,%1,%2,%3};"
        : "+f"(c[0]), "+f"(c[1]), "+f"(c[2]), "+f"(c[3])
        : "r"(a[0]), "r"(a[1]), "r"(a[2]), "r"(a[3]), "r"(b[0]), "r"(b[1]));
}

// ---- bf16 helpers ----
__device__ __forceinline__ void mmabf(float* c, const uint32_t* a, const uint32_t* b) {
    asm volatile(
        "mma.sync.aligned.m16n8k16.row.col.f32.bf16.bf16.f32 "
        "{%0,%1,%2,%3}, {%4,%5,%6,%7}, {%8,%9}, {%0,%1,%2,%3};"
        : "+f"(c[0]), "+f"(c[1]), "+f"(c[2]), "+f"(c[3])
        : "r"(a[0]), "r"(a[1]), "r"(a[2]), "r"(a[3]), "r"(b[0]), "r"(b[1]));
}
__device__ __forceinline__ void bfsplit(float v, __nv_bfloat16& h, __nv_bfloat16& l) {
    h = __float2bfloat16_rn(v);
    l = __float2bfloat16_rn(v - __bfloat162float(h));
}
__device__ __forceinline__ uint32_t bfpack(__nv_bfloat16 a, __nv_bfloat16 b) {
    unsigned short ua = *reinterpret_cast<unsigned short*>(&a);
    unsigned short ub = *reinterpret_cast<unsigned short*>(&b);
    return (uint32_t)ua | ((uint32_t)ub << 16);
}
// pack hi pair, output lo pair
__device__ __forceinline__ uint32_t packsplit(float a, float b, uint32_t& lopk) {
    __nv_bfloat16 ha, la, hb, lb;
    bfsplit(a, ha, la);
    bfsplit(b, hb, lb);
    lopk = bfpack(la, lb);
    return bfpack(ha, hb);
}

// ---------------------------------------------------------------------------
// Fused projection via mma.sync tf32, 3-term hi/lo split (mainloop = R5/R6).
// Epilogue now emits bf16 hi/lo planes: q,k row-major; v transposed.
// Q pre-scaled by 1/sqrt(HD).
// ---------------------------------------------------------------------------
#define PJ_STAGE_FLOATS (128 * 36 + 3 * 32 * 68)
#define PJ_SMEM_BYTES (2 * PJ_STAGE_FLOATS * 4)

__device__ __forceinline__ void pj_stage_cp(float* stg, const float* __restrict__ x,
                                            const float* const* Ws,
                                            int row0, int k0, int tid)
{
    float* xs = stg;
    float* ws = stg + 128 * 36;
    #pragma unroll
    for (int t = 0; t < 4; t++) {
        int idx = tid + t * 256;
        int r = idx >> 3, cq = idx & 7;
        cp16(s2u(xs + r * 36 + cq * 4),
             &x[(size_t)(row0 + r) * EMB + k0 + cq * 4]);
    }
    #pragma unroll
    for (int t = 0; t < 6; t++) {
        int idx = tid + t * 256;
        int mat = idx >> 9, rem = idx & 511;
        int kk = rem >> 4, nq = rem & 15;
        cp16(s2u(ws + (mat * 32 + kk) * 68 + nq * 4),
             &Ws[mat][(size_t)(k0 + kk) * HD + nq * 4]);
    }
    asm volatile("cp.async.commit_group;" ::: "memory");
}

__global__ __launch_bounds__(256) void proj_mma_kernel(
    const float* __restrict__ x,
    const float* __restrict__ Wq,
    const float* __restrict__ Wk,
    const float* __restrict__ Wv)
{
    extern __shared__ float psm[];
    const int tid = threadIdx.x;
    const int lane = tid & 31;
    const int wid = tid >> 5;
    const int wr = wid >> 1;
    const int wc = wid & 1;
    const int row0 = blockIdx.x * 128;
    const int g = lane >> 2;
    const int t4 = lane & 3;

    const float* Ws[3] = {Wq, Wk, Wv};

    float C[2][12][4];
    #pragma unroll
    for (int mt = 0; mt < 2; mt++)
        #pragma unroll
        for (int nt = 0; nt < 12; nt++)
            #pragma unroll
            for (int i = 0; i < 4; i++) C[mt][nt][i] = 0.0f;

    pj_stage_cp(psm, x, Ws, row0, 0, tid);
    pj_stage_cp(psm + PJ_STAGE_FLOATS, x, Ws, row0, 32, tid);

    for (int s = 0; s < 24; s++) {
        float* stg = psm + (s & 1) * PJ_STAGE_FLOATS;
        float* xs = stg;
        float* ws = stg + 128 * 36;

        if (s < 23) asm volatile("cp.async.wait_group 1;" ::: "memory");
        else        asm volatile("cp.async.wait_group 0;" ::: "memory");
        __syncthreads();

        #pragma unroll
        for (int ks = 0; ks < 4; ks++) {
            uint32_t ahi[2][4], alo[2][4];
            #pragma unroll
            for (int mt = 0; mt < 2; mt++) {
                int rb = wr * 32 + mt * 16 + g;
                int cb = ks * 8 + t4;
                hilo(xs[rb * 36 + cb],           ahi[mt][0], alo[mt][0]);
                hilo(xs[(rb + 8) * 36 + cb],     ahi[mt][1], alo[mt][1]);
                hilo(xs[rb * 36 + cb + 4],       ahi[mt][2], alo[mt][2]);
                hilo(xs[(rb + 8) * 36 + cb + 4], ahi[mt][3], alo[mt][3]);
            }
            #pragma unroll
            for (int nt = 0; nt < 12; nt++) {
                int gn = wc * 96 + nt * 8;
                int mat = gn >> 6;
                int ncol = (gn & 63) + g;
                const float* wb = ws + (mat * 32 + ks * 8) * 68 + ncol;
                uint32_t bhi[2], blo[2];
                hilo(wb[t4 * 68],       bhi[0], blo[0]);
                hilo(wb[(t4 + 4) * 68], bhi[1], blo[1]);
                #pragma unroll
                for (int mt = 0; mt < 2; mt++) {
                    mma8(C[mt][nt], ahi[mt], bhi);
                    mma8(C[mt][nt], ahi[mt], blo);
                    mma8(C[mt][nt], alo[mt], bhi);
                }
            }
        }
        __syncthreads();

        if (s + 2 < 24)
            pj_stage_cp(psm + (s & 1) * PJ_STAGE_FLOATS, x, Ws, row0, (s + 2) * 32, tid);
    }

    // Epilogue: bf16 hi/lo plane stores
    #pragma unroll
    for (int mt = 0; mt < 2; mt++) {
        #pragma unroll
        for (int nt = 0; nt < 12; nt++) {
            int gn = wc * 96 + nt * 8;
            int mat = gn >> 6;
            int col = (gn & 63) + t4 * 2;
            int row = row0 + wr * 32 + mt * 16 + g;
            float c0 = C[mt][nt][0], c1 = C[mt][nt][1];
            float c2 = C[mt][nt][2], c3 = C[mt][nt][3];
            if (mat == 0) {
                uint32_t lo, hi;
                hi = packsplit(0.125f * c0, 0.125f * c1, lo);
                *reinterpret_cast<uint32_t*>(&g_qh[(size_t)row * HD + col]) = hi;
                *reinterpret_cast<uint32_t*>(&g_ql[(size_t)row * HD + col]) = lo;
                hi = packsplit(0.125f * c2, 0.125f * c3, lo);
                *reinterpret_cast<uint32_t*>(&g_qh[(size_t)(row + 8) * HD + col]) = hi;
                *reinterpret_cast<uint32_t*>(&g_ql[(size_t)(row + 8) * HD + col]) = lo;
            } else if (mat == 1) {
                uint32_t lo, hi;
                hi = packsplit(c0, c1, lo);
                *reinterpret_cast<uint32_t*>(&g_kh[(size_t)row * HD + col]) = hi;
                *reinterpret_cast<uint32_t*>(&g_kl[(size_t)row * HD + col]) = lo;
                hi = packsplit(c2, c3, lo);
                *reinterpret_cast<uint32_t*>(&g_kh[(size_t)(row + 8) * HD + col]) = hi;
                *reinterpret_cast<uint32_t*>(&g_kl[(size_t)(row + 8) * HD + col]) = lo;
            } else {
                int bb = row >> 12;
                int tok = row & (SEQT - 1);
                size_t b0 = (size_t)(bb * HD + col) * SEQT + tok;
                size_t b1 = b0 + SEQT;  // col+1
                __nv_bfloat16 h, l;
                bfsplit(c0, h, l); g_vh[b0] = h;     g_vl[b0] = l;
                bfsplit(c1, h, l); g_vh[b1] = h;     g_vl[b1] = l;
                bfsplit(c2, h, l); g_vh[b0 + 8] = h; g_vl[b0 + 8] = l;
                bfsplit(c3, h, l); g_vh[b1 + 8] = h; g_vl[b1 + 8] = l;
            }
        }
    }
}

// ---------------------------------------------------------------------------
// Flash attention (causal) via mma.sync bf16 m16n8k16, 3-term Ootomo split.
// All operands pre-split into bf16 hi/lo planes (zero CVT in mainloop).
// Split-K schedule unchanged: grid (96, B); 8 warps (4 mw x 2 nw).
// Smem rows: 36-u32 pitch -> all fragment LDS / P STS conflict-free.
// ---------------------------------------------------------------------------
#define PW 36
#define OFF_QH 0
#define OFF_QL 2304
#define OFF_K  4608    // per buf: 4608 u32 (hi 2304, lo 2304); 2 bufs
#define OFF_V  13824
#define OFF_PH 23040
#define OFF_PL 25344
#define OFF_WMX 27648
#define OFF_WSM 27776
#define ATTN_SMEM_U32 27904
#define ATTN_SMEM_BYTES (ATTN_SMEM_U32 * 4)

__device__ __forceinline__ void tile_cpb(uint32_t* smu, int buf, int kt,
    const __nv_bfloat16* Kh, const __nv_bfloat16* Kl,
    const __nv_bfloat16* Vh, const __nv_bfloat16* Vl, int tid)
{
    uint32_t* kb = smu + OFF_K + buf * 4608;
    uint32_t* vb = smu + OFF_V + buf * 4608;
    #pragma unroll
    for (int t = 0; t < 4; t++) {
        int idx = tid + t * 256;
        int pl = idx >> 9, rem = idx & 511, tok = rem >> 3, q = rem & 7;
        const __nv_bfloat16* s = (pl ? Kl : Kh) + (size_t)(kt * 64 + tok) * HD + q * 8;
        cp16(s2u(kb + pl * 2304 + tok * PW + q * 4), s);
    }
    #pragma unroll
    for (int t = 0; t < 4; t++) {
        int idx = tid + t * 256;
        int pl = idx >> 9, rem = idx & 511, d = rem >> 3, q = rem & 7;
        const __nv_bfloat16* s = (pl ? Vl : Vh) + (size_t)d * SEQT + kt * 64 + q * 8;
        cp16(s2u(vb + pl * 2304 + d * PW + q * 4), s);
    }
    asm volatile("cp.async.commit_group;" ::: "memory");
}

__global__ __launch_bounds__(256, 2) void attn_mma_kernel(float* __restrict__ out)
{
    extern __shared__ uint32_t smu[];
    float* Wmx = reinterpret_cast<float*>(smu + OFF_WMX);  // [2][64]
    float* Wsm = reinterpret_cast<float*>(smu + OFF_WSM);  // [2][64]

    const int tid = threadIdx.x;
    const int lane = tid & 31;
    const int wid = tid >> 5;
    const int mw = wid >> 1;
    const int nw = wid & 1;
    const int g = lane >> 2;
    const int t4 = lane & 3;
    const int b = blockIdx.y;
    const int i0 = blockIdx.x;

    int qi, k0t, k1t, part;
    bool partial;
    if (i0 < 64) {
        qi = 63 - (i0 >> 1);
        part = i0 & 1;
        int hs = (qi + 1) >> 1;
        if (part == 0) { k0t = 0;  k1t = hs - 1; }
        else           { k0t = hs; k1t = qi; }
        partial = true;
    } else {
        qi = 95 - i0; part = 0; k0t = 0; k1t = qi; partial = false;
    }

    const __nv_bfloat16* Kh = g_kh + (size_t)b * SEQT * HD;
    const __nv_bfloat16* Kl = g_kl + (size_t)b * SEQT * HD;
    const __nv_bfloat16* Vh = g_vh + (size_t)b * HD * SEQT;
    const __nv_bfloat16* Vl = g_vl + (size_t)b * HD * SEQT;

    tile_cpb(smu, k0t & 1, k0t, Kh, Kl, Vh, Vl, tid);
    if (k0t + 1 <= k1t)
        tile_cpb(smu, (k0t + 1) & 1, k0t + 1, Kh, Kl, Vh, Vl, tid);

    // Q tile load (planes already pre-scaled by 1/sqrt(HD))
    {
        const __nv_bfloat16* Qh = g_qh + ((size_t)b * SEQT + qi * 64) * HD;
        const __nv_bfloat16* Ql = g_ql + ((size_t)b * SEQT + qi * 64) * HD;
        #pragma unroll
        for (int t = 0; t < 4; t++) {
            int idx = tid + t * 256;
            int pl = idx >> 9, rem = idx & 511, row = rem >> 3, q = rem & 7;
            const __nv_bfloat16* src = (pl ? Ql : Qh) + (size_t)row * HD + q * 8;
            float4 v = *reinterpret_cast<const float4*>(src);
            *reinterpret_cast<float4*>(smu + pl * 2304 + row * PW + q * 4) = v;
        }
    }

    const int r0 = 16 * mw + g;
    float rm0 = -CUDART_INF_F, rm1 = -CUDART_INF_F;
    float rs0 = 0.0f, rs1 = 0.0f;
    float O[4][4];
    #pragma unroll
    for (int nt = 0; nt < 4; nt++)
        #pragma unroll
        for (int i = 0; i < 4; i++) O[nt][i] = 0.0f;

    for (int kt = k0t; kt <= k1t; kt++) {
        uint32_t* Kb = smu + OFF_K + (kt & 1) * 4608;
        uint32_t* Vb = smu + OFF_V + (kt & 1) * 4608;

        if (kt < k1t) asm volatile("cp.async.wait_group 1;" ::: "memory");
        else          asm volatile("cp.async.wait_group 0;" ::: "memory");
        __syncthreads();

        // ---- S = Q K^T (3-term bf16, k16) ----
        float S[4][4];
        #pragma unroll
        for (int nt = 0; nt < 4; nt++)
            #pragma unroll
            for (int i = 0; i < 4; i++) S[nt][i] = 0.0f;

        #pragma unroll
        for (int ks = 0; ks < 4; ks++) {
            int ab = r0 * PW + 8 * ks + t4;
            uint32_t ah[4], al[4];
            ah[0] = smu[ab];            ah[1] = smu[ab + 8 * PW];
            ah[2] = smu[ab + 4];        ah[3] = smu[ab + 8 * PW + 4];
            al[0] = smu[2304 + ab];     al[1] = smu[2304 + ab + 8 * PW];
            al[2] = smu[2304 + ab + 4]; al[3] = smu[2304 + ab + 8 * PW + 4];
            #pragma unroll
            for (int nt = 0; nt < 4; nt++) {
                int tok = 32 * nw + 8 * nt + g;
                int bb2 = tok * PW + 8 * ks + t4;
                uint32_t bh[2] = {Kb[bb2], Kb[bb2 + 4]};
                uint32_t bl[2] = {Kb[2304 + bb2], Kb[2304 + bb2 + 4]};
                mmabf(S[nt], ah, bh);
                mmabf(S[nt], ah, bl);
                mmabf(S[nt], al, bh);
            }
        }

        // ---- causal mask on diagonal tile ----
        if (kt == qi) {
            #pragma unroll
            for (int nt = 0; nt < 4; nt++) {
                int colb = 32 * nw + 8 * nt + 2 * t4;
                if (colb     > r0)     S[nt][0] = -CUDART_INF_F;
                if (colb + 1 > r0)     S[nt][1] = -CUDART_INF_F;
                if (colb     > r0 + 8) S[nt][2] = -CUDART_INF_F;
                if (colb + 1 > r0 + 8) S[nt][3] = -CUDART_INF_F;
            }
        }

        // ---- row max (warp partial + cross-warp via smem) ----
        float m0 = fmaxf(fmaxf(S[0][0], S[0][1]), fmaxf(S[1][0], S[1][1]));
        m0 = fmaxf(m0, fmaxf(fmaxf(S[2][0], S[2][1]), fmaxf(S[3][0], S[3][1])));
        float m1 = fmaxf(fmaxf(S[0][2], S[0][3]), fmaxf(S[1][2], S[1][3]));
        m1 = fmaxf(m1, fmaxf(fmaxf(S[2][2], S[2][3]), fmaxf(S[3][2], S[3][3])));
        m0 = fmaxf(m0, __shfl_xor_sync(0xffffffffu, m0, 1));
        m0 = fmaxf(m0, __shfl_xor_sync(0xffffffffu, m0, 2));
        m1 = fmaxf(m1, __shfl_xor_sync(0xffffffffu, m1, 1));
        m1 = fmaxf(m1, __shfl_xor_sync(0xffffffffu, m1, 2));
        if (t4 == 0) {
            Wmx[nw * 64 + r0] = m0;
            Wmx[nw * 64 + r0 + 8] = m1;
        }
        __syncthreads();

        float nm0 = fmaxf(rm0, fmaxf(Wmx[r0], Wmx[64 + r0]));
        float nm1 = fmaxf(rm1, fmaxf(Wmx[r0 + 8], Wmx[64 + r0 + 8]));
        float alpha0 = __expf(rm0 - nm0);
        float alpha1 = __expf(rm1 - nm1);
        rm0 = nm0; rm1 = nm1;

        // ---- p = exp(s - nm), bf16-split into P planes, partial sums ----
        float sum0 = 0.0f, sum1 = 0.0f;
        #pragma unroll
        for (int nt = 0; nt < 4; nt++) {
            float p00 = __expf(S[nt][0] - nm0);
            float p01 = __expf(S[nt][1] - nm0);
            float p10 = __expf(S[nt][2] - nm1);
            float p11 = __expf(S[nt][3] - nm1);
            sum0 += p00 + p01;
            sum1 += p10 + p11;
            int pc = 16 * nw + 4 * nt + t4;
            uint32_t lo, hi;
            hi = packsplit(p00, p01, lo);
            smu[OFF_PH + r0 * PW + pc] = hi;
            smu[OFF_PL + r0 * PW + pc] = lo;
            hi = packsplit(p10, p11, lo);
            smu[OFF_PH + (r0 + 8) * PW + pc] = hi;
            smu[OFF_PL + (r0 + 8) * PW + pc] = lo;
        }
        sum0 += __shfl_xor_sync(0xffffffffu, sum0, 1);
        sum0 += __shfl_xor_sync(0xffffffffu, sum0, 2);
        sum1 += __shfl_xor_sync(0xffffffffu, sum1, 1);
        sum1 += __shfl_xor_sync(0xffffffffu, sum1, 2);
        if (t4 == 0) {
            Wsm[nw * 64 + r0] = sum0;
            Wsm[nw * 64 + r0 + 8] = sum1;
        }
        __syncthreads();

        rs0 = rs0 * alpha0 + Wsm[r0] + Wsm[64 + r0];
        rs1 = rs1 * alpha1 + Wsm[r0 + 8] + Wsm[64 + r0 + 8];

        #pragma unroll
        for (int nt = 0; nt < 4; nt++) {
            O[nt][0] *= alpha0; O[nt][1] *= alpha0;
            O[nt][2] *= alpha1; O[nt][3] *= alpha1;
        }

        // ---- O += P @ V (3-term bf16, k16; V transposed in smem) ----
        #pragma unroll
        for (int ks = 0; ks < 4; ks++) {
            int ab = r0 * PW + 8 * ks + t4;
            uint32_t ah[4], al[4];
            ah[0] = smu[OFF_PH + ab];     ah[1] = smu[OFF_PH + ab + 8 * PW];
            ah[2] = smu[OFF_PH + ab + 4]; ah[3] = smu[OFF_PH + ab + 8 * PW + 4];
            al[0] = smu[OFF_PL + ab];     al[1] = smu[OFF_PL + ab + 8 * PW];
            al[2] = smu[OFF_PL + ab + 4]; al[3] = smu[OFF_PL + ab + 8 * PW + 4];
            #pragma unroll
            for (int nt = 0; nt < 4; nt++) {
                int d = 32 * nw + 8 * nt + g;
                int vb2 = d * PW + 8 * ks + t4;
                uint32_t bh[2] = {Vb[vb2], Vb[vb2 + 4]};
                uint32_t bl[2] = {Vb[2304 + vb2], Vb[2304 + vb2 + 4]};
                mmabf(O[nt], ah, bh);
                mmabf(O[nt], ah, bl);
                mmabf(O[nt], al, bh);
            }
        }
        __syncthreads();

        if (kt + 2 <= k1t)
            tile_cpb(smu, (kt & 1), kt + 2, Kh, Kl, Vh, Vl, tid);
    }

    // ---- epilogue ----
    if (!partial) {
        float inv0 = 1.0f / rs0, inv1 = 1.0f / rs1;
        #pragma unroll
        for (int nt = 0; nt < 4; nt++) {
            int col = 32 * nw + 8 * nt + 2 * t4;
            size_t row = (size_t)b * SEQT + qi * 64 + r0;
            *reinterpret_cast<float2*>(&out[row * HD + col]) =
                make_float2(O[nt][0] * inv0, O[nt][1] * inv0);
            *reinterpret_cast<float2*>(&out[(row + 8) * HD + col]) =
                make_float2(O[nt][2] * inv1, O[nt][3] * inv1);
        }
    } else {
        int gr = b * SEQT + qi * 64 + r0;
        #pragma unroll
        for (int nt = 0; nt < 4; nt++) {
            int col = 32 * nw + 8 * nt + 2 * t4;
            *reinterpret_cast<float2*>(&g_po[part][(size_t)gr * HD + col]) =
                make_float2(O[nt][0], O[nt][1]);
            *reinterpret_cast<float2*>(&g_po[part][(size_t)(gr + 8) * HD + col]) =
                make_float2(O[nt][2], O[nt][3]);
        }
        if (nw == 0 && t4 == 0) {
            g_pm[part][gr] = rm0;     g_pl[part][gr] = rs0;
            g_pm[part][gr + 8] = rm1; g_pl[part][gr + 8] = rs1;
        }
    }
}

// ---------------------------------------------------------------------------
// Combine split-K partials (rows with qi >= 32). (unchanged)
// ---------------------------------------------------------------------------
__global__ __launch_bounds__(256) void combine_kernel(float* __restrict__ out)
{
    int idx = blockIdx.x * 256 + threadIdx.x;
    int hr = idx >> 4;
    int c4 = (idx & 15) << 2;
    int b = hr >> 11;
    int r = 2048 + (hr & 2047);
    int gr = b * SEQT + r;

    float m0 = g_pm[0][gr], m1 = g_pm[1][gr];
    float M = fmaxf(m0, m1);
    float e0 = __expf(m0 - M), e1 = __expf(m1 - M);
    float den = e0 * g_pl[0][gr] + e1 * g_pl[1][gr];
    float inv = 1.0f / den;

    float4 a = *reinterpret_cast<float4*>(&g_po[0][(size_t)gr * HD + c4]);
    float4 c = *reinterpret_cast<float4*>(&g_po[1][(size_t)gr * HD + c4]);
    float4 o;
    o.x = (e0 * a.x + e1 * c.x) * inv;
    o.y = (e0 * a.y + e1 * c.y) * inv;
    o.z = (e0 * a.z + e1 * c.z) * inv;
    o.w = (e0 * a.w + e1 * c.w) * inv;
    *reinterpret_cast<float4*>(&out[(size_t)gr * HD + c4]) = o;
}

extern "C" void kernel_launch(void* const* d_in, const int* in_sizes, int n_in,
                              void* d_out, int out_size) {
    (void)in_sizes; (void)n_in; (void)out_size;
    const float* x  = (const float*)d_in[0];
    const float* Wk = (const float*)d_in[1];
    const float* Wq = (const float*)d_in[2];
    const float* Wv = (const float*)d_in[3];
    float* out = (float*)d_out;

    cudaFuncSetAttribute(proj_mma_kernel,
                         cudaFuncAttributeMaxDynamicSharedMemorySize,
                         PJ_SMEM_BYTES);
    proj_mma_kernel<<<BT / 128, 256, PJ_SMEM_BYTES>>>(x, Wq, Wk, Wv);

    cudaFuncSetAttribute(attn_mma_kernel,
                         cudaFuncAttributeMaxDynamicSharedMemorySize,
                         ATTN_SMEM_BYTES);
    dim3 ag(96, BATCH);
    attn_mma_kernel<<<ag, 256, ATTN_SMEM_BYTES>>>(out);

    combine_kernel<<<512, 256>>>(out);
}

// round 8
// speedup vs baseline: 3.1636x; 1.1776x over previous
#include <cuda_runtime.h>
#include <cuda_bf16.h>
#include <math_constants.h>
#include <cstdint>

#define BATCH 4
#define SEQT 4096
#define EMB 768
#define HD 64
#define BT (BATCH * SEQT)

typedef unsigned long long ull;

// Scratch (device globals: no allocation allowed)
// q/k planes: row-major [token][d], bf16 hi/lo. v planes: TRANSPOSED
// [(b*HD + d)][token], bf16 hi/lo.
__device__ __nv_bfloat16 g_qh[BT * HD], g_ql[BT * HD];
__device__ __nv_bfloat16 g_kh[BT * HD], g_kl[BT * HD];
__device__ __nv_bfloat16 g_vh[BT * HD], g_vl[BT * HD];
// W planes: [mat][n][k] (transposed), bf16 hi/lo.
__device__ __nv_bfloat16 g_wth[3 * 64 * EMB], g_wtl[3 * 64 * EMB];
__device__ float g_po[2][BT * HD];  // split-K partial numerators
__device__ float g_pm[2][BT];       // split-K partial row max
__device__ float g_pl[2][BT];       // split-K partial row sum

__device__ __forceinline__ uint32_t s2u(const void* p) {
    return (uint32_t)__cvta_generic_to_shared(p);
}
__device__ __forceinline__ void cp16(uint32_t dst, const void* src) {
    asm volatile("cp.async.ca.shared.global [%0], [%1], 16;" :: "r"(dst), "l"(src));
}

// ---- bf16 helpers ----
__device__ __forceinline__ void mmabf(float* c, const uint32_t* a, const uint32_t* b) {
    asm volatile(
        "mma.sync.aligned.m16n8k16.row.col.f32.bf16.bf16.f32 "
        "{%0,%1,%2,%3}, {%4,%5,%6,%7}, {%8,%9}, {%0,%1,%2,%3};"
        : "+f"(c[0]), "+f"(c[1]), "+f"(c[2]), "+f"(c[3])
        : "r"(a[0]), "r"(a[1]), "r"(a[2]), "r"(a[3]), "r"(b[0]), "r"(b[1]));
}
__device__ __forceinline__ void bfsplit(float v, __nv_bfloat16& h, __nv_bfloat16& l) {
    h = __float2bfloat16_rn(v);
    l = __float2bfloat16_rn(v - __bfloat162float(h));
}
__device__ __forceinline__ uint32_t bfpack(__nv_bfloat16 a, __nv_bfloat16 b) {
    unsigned short ua = *reinterpret_cast<unsigned short*>(&a);
    unsigned short ub = *reinterpret_cast<unsigned short*>(&b);
    return (uint32_t)ua | ((uint32_t)ub << 16);
}
__device__ __forceinline__ uint32_t packsplit(float a, float b, uint32_t& lopk) {
    __nv_bfloat16 ha, la, hb, lb;
    bfsplit(a, ha, la);
    bfsplit(b, hb, lb);
    lopk = bfpack(la, lb);
    return bfpack(ha, hb);
}

// ---------------------------------------------------------------------------
// W pre-split: W[k][n] fp32 -> g_wth/g_wtl [mat][n][k] bf16 planes.
// 147456 elements, grid 576 x 256.
// ---------------------------------------------------------------------------
__global__ __launch_bounds__(256) void wsplit_kernel(
    const float* __restrict__ Wq,
    const float* __restrict__ Wk,
    const float* __restrict__ Wv)
{
    int idx = blockIdx.x * 256 + threadIdx.x;
    int mat = idx / (64 * EMB);
    int rem = idx - mat * 64 * EMB;
    int n = rem / EMB;
    int k = rem - n * EMB;
    const float* W = (mat == 0) ? Wq : ((mat == 1) ? Wk : Wv);
    float v = W[(size_t)k * HD + n];
    __nv_bfloat16 h, l;
    bfsplit(v, h, l);
    g_wth[idx] = h;
    g_wtl[idx] = l;
}

// ---------------------------------------------------------------------------
// Fused projection, all-bf16 m16n8k16 3-term.
// grid 128 (M=128/CTA), 256 threads = 8 warps (wr=wid>>1 m, wc=wid&1 n).
// Per stage (K=32): cp.async x fp32 + W bf16 planes; batched x->bf16 convert;
// then 144 mma/warp. Smem pitches: x fp32 36 f32; bf16 planes 20 u32.
// Epilogue identical to R7 (bf16 hi/lo q/k row-major, v transposed; q *0.125).
// ---------------------------------------------------------------------------
#define XF_OFF 0          // 2 x 128*36 u32 (fp32 x staging)
#define XP_OFF 9216       // hi 128*20, lo 128*20
#define WP_OFF 14336      // 2 bufs x (hi 192*20 + lo 192*20)
#define PJ2_SMEM_U32 29696
#define PJ2_SMEM_BYTES (PJ2_SMEM_U32 * 4)

__device__ __forceinline__ void pj2_cp(uint32_t* smu, int buf,
                                       const float* __restrict__ x,
                                       int row0, int k0, int tid)
{
    uint32_t* xf = smu + XF_OFF + buf * 4608;
    #pragma unroll
    for (int t = 0; t < 4; t++) {
        int idx = tid + t * 256;
        int r = idx >> 3, c = idx & 7;
        cp16(s2u(xf + r * 36 + c * 4), &x[(size_t)(row0 + r) * EMB + k0 + c * 4]);
    }
    uint32_t* wp = smu + WP_OFF + buf * 7680;
    #pragma unroll
    for (int t = 0; t < 6; t++) {
        int idx = tid + t * 256;
        int pl = (idx >= 768) ? 1 : 0;
        int rem = idx - pl * 768;
        int row = rem >> 2, chunk = rem & 3;
        const __nv_bfloat16* src =
            (pl ? g_wtl : g_wth) + (size_t)row * EMB + k0 + chunk * 8;
        cp16(s2u(wp + pl * 3840 + row * 20 + chunk * 4), src);
    }
    asm volatile("cp.async.commit_group;" ::: "memory");
}

__global__ __launch_bounds__(256) void proj_bf16_kernel(const float* __restrict__ x)
{
    extern __shared__ uint32_t smu[];
    const int tid = threadIdx.x;
    const int lane = tid & 31;
    const int wid = tid >> 5;
    const int wr = wid >> 1;
    const int wc = wid & 1;
    const int row0 = blockIdx.x * 128;
    const int g = lane >> 2;
    const int t4 = lane & 3;

    float C[2][12][4];
    #pragma unroll
    for (int mt = 0; mt < 2; mt++)
        #pragma unroll
        for (int nt = 0; nt < 12; nt++)
            #pragma unroll
            for (int i = 0; i < 4; i++) C[mt][nt][i] = 0.0f;

    pj2_cp(smu, 0, x, row0, 0, tid);
    pj2_cp(smu, 1, x, row0, 32, tid);

    for (int s = 0; s < 24; s++) {
        const int buf = s & 1;

        if (s < 23) asm volatile("cp.async.wait_group 1;" ::: "memory");
        else        asm volatile("cp.async.wait_group 0;" ::: "memory");
        __syncthreads();

        // Batched convert: fp32 x tile -> bf16 hi/lo planes (once per element)
        {
            const uint32_t* xf = smu + XF_OFF + buf * 4608;
            uint32_t* xph = smu + XP_OFF;
            uint32_t* xpl = smu + XP_OFF + 2560;
            #pragma unroll
            for (int t = 0; t < 4; t++) {
                int idx = tid + t * 256;
                int r = idx >> 3, c = idx & 7;
                float4 v = *reinterpret_cast<const float4*>(xf + r * 36 + c * 4);
                uint32_t lo0, lo1;
                uint32_t h0 = packsplit(v.x, v.y, lo0);
                uint32_t h1 = packsplit(v.z, v.w, lo1);
                xph[r * 20 + c * 2] = h0;
                xph[r * 20 + c * 2 + 1] = h1;
                xpl[r * 20 + c * 2] = lo0;
                xpl[r * 20 + c * 2 + 1] = lo1;
            }
        }
        __syncthreads();

        // MMA phase: 2 k16-steps x 12 nt x 2 mt x 3 terms
        {
            const uint32_t* xph = smu + XP_OFF;
            const uint32_t* xpl = smu + XP_OFF + 2560;
            const uint32_t* wph = smu + WP_OFF + buf * 7680;
            const uint32_t* wpl = wph + 3840;
            #pragma unroll
            for (int ks = 0; ks < 2; ks++) {
                uint32_t ah[2][4], al[2][4];
                #pragma unroll
                for (int mt = 0; mt < 2; mt++) {
                    int ab = (wr * 32 + mt * 16 + g) * 20 + ks * 8 + t4;
                    ah[mt][0] = xph[ab];       ah[mt][1] = xph[ab + 160];
                    ah[mt][2] = xph[ab + 4];   ah[mt][3] = xph[ab + 164];
                    al[mt][0] = xpl[ab];       al[mt][1] = xpl[ab + 160];
                    al[mt][2] = xpl[ab + 4];   al[mt][3] = xpl[ab + 164];
                }
                #pragma unroll
                for (int nt = 0; nt < 12; nt++) {
                    int gcol = wc * 96 + nt * 8 + g;
                    int bb = gcol * 20 + ks * 8 + t4;
                    uint32_t bh[2] = {wph[bb], wph[bb + 4]};
                    uint32_t bl[2] = {wpl[bb], wpl[bb + 4]};
                    #pragma unroll
                    for (int mt = 0; mt < 2; mt++) {
                        mmabf(C[mt][nt], ah[mt], bh);
                        mmabf(C[mt][nt], ah[mt], bl);
                        mmabf(C[mt][nt], al[mt], bh);
                    }
                }
            }
        }
        __syncthreads();

        if (s + 2 < 24)
            pj2_cp(smu, buf, x, row0, (s + 2) * 32, tid);
    }

    // Epilogue (identical to R7): bf16 hi/lo plane stores
    #pragma unroll
    for (int mt = 0; mt < 2; mt++) {
        #pragma unroll
        for (int nt = 0; nt < 12; nt++) {
            int gn = wc * 96 + nt * 8;
            int mat = gn >> 6;
            int col = (gn & 63) + t4 * 2;
            int row = row0 + wr * 32 + mt * 16 + g;
            float c0 = C[mt][nt][0], c1 = C[mt][nt][1];
            float c2 = C[mt][nt][2], c3 = C[mt][nt][3];
            if (mat == 0) {
                uint32_t lo, hi;
                hi = packsplit(0.125f * c0, 0.125f * c1, lo);
                *reinterpret_cast<uint32_t*>(&g_qh[(size_t)row * HD + col]) = hi;
                *reinterpret_cast<uint32_t*>(&g_ql[(size_t)row * HD + col]) = lo;
                hi = packsplit(0.125f * c2, 0.125f * c3, lo);
                *reinterpret_cast<uint32_t*>(&g_qh[(size_t)(row + 8) * HD + col]) = hi;
                *reinterpret_cast<uint32_t*>(&g_ql[(size_t)(row + 8) * HD + col]) = lo;
            } else if (mat == 1) {
                uint32_t lo, hi;
                hi = packsplit(c0, c1, lo);
                *reinterpret_cast<uint32_t*>(&g_kh[(size_t)row * HD + col]) = hi;
                *reinterpret_cast<uint32_t*>(&g_kl[(size_t)row * HD + col]) = lo;
                hi = packsplit(c2, c3, lo);
                *reinterpret_cast<uint32_t*>(&g_kh[(size_t)(row + 8) * HD + col]) = hi;
                *reinterpret_cast<uint32_t*>(&g_kl[(size_t)(row + 8) * HD + col]) = lo;
            } else {
                int bb = row >> 12;
                int tok = row & (SEQT - 1);
                size_t b0 = (size_t)(bb * HD + col) * SEQT + tok;
                size_t b1 = b0 + SEQT;  // col+1
                __nv_bfloat16 h, l;
                bfsplit(c0, h, l); g_vh[b0] = h;     g_vl[b0] = l;
                bfsplit(c1, h, l); g_vh[b1] = h;     g_vl[b1] = l;
                bfsplit(c2, h, l); g_vh[b0 + 8] = h; g_vl[b0 + 8] = l;
                bfsplit(c3, h, l); g_vh[b1 + 8] = h; g_vl[b1 + 8] = l;
            }
        }
    }
}

// ---------------------------------------------------------------------------
// Flash attention (causal) via mma.sync bf16 m16n8k16, 3-term. (unchanged R7)
// ---------------------------------------------------------------------------
#define PW 36
#define OFF_K  4608
#define OFF_V  13824
#define OFF_PH 23040
#define OFF_PL 25344
#define OFF_WMX 27648
#define OFF_WSM 27776
#define ATTN_SMEM_U32 27904
#define ATTN_SMEM_BYTES (ATTN_SMEM_U32 * 4)

__device__ __forceinline__ void tile_cpb(uint32_t* smu, int buf, int kt,
    const __nv_bfloat16* Kh, const __nv_bfloat16* Kl,
    const __nv_bfloat16* Vh, const __nv_bfloat16* Vl, int tid)
{
    uint32_t* kb = smu + OFF_K + buf * 4608;
    uint32_t* vb = smu + OFF_V + buf * 4608;
    #pragma unroll
    for (int t = 0; t < 4; t++) {
        int idx = tid + t * 256;
        int pl = idx >> 9, rem = idx & 511, tok = rem >> 3, q = rem & 7;
        const __nv_bfloat16* s = (pl ? Kl : Kh) + (size_t)(kt * 64 + tok) * HD + q * 8;
        cp16(s2u(kb + pl * 2304 + tok * PW + q * 4), s);
    }
    #pragma unroll
    for (int t = 0; t < 4; t++) {
        int idx = tid + t * 256;
        int pl = idx >> 9, rem = idx & 511, d = rem >> 3, q = rem & 7;
        const __nv_bfloat16* s = (pl ? Vl : Vh) + (size_t)d * SEQT + kt * 64 + q * 8;
        cp16(s2u(vb + pl * 2304 + d * PW + q * 4), s);
    }
    asm volatile("cp.async.commit_group;" ::: "memory");
}

__global__ __launch_bounds__(256, 2) void attn_mma_kernel(float* __restrict__ out)
{
    extern __shared__ uint32_t smu[];
    float* Wmx = reinterpret_cast<float*>(smu + OFF_WMX);
    float* Wsm = reinterpret_cast<float*>(smu + OFF_WSM);

    const int tid = threadIdx.x;
    const int lane = tid & 31;
    const int wid = tid >> 5;
    const int mw = wid >> 1;
    const int nw = wid & 1;
    const int g = lane >> 2;
    const int t4 = lane & 3;
    const int b = blockIdx.y;
    const int i0 = blockIdx.x;

    int qi, k0t, k1t, part;
    bool partial;
    if (i0 < 64) {
        qi = 63 - (i0 >> 1);
        part = i0 & 1;
        int hs = (qi + 1) >> 1;
        if (part == 0) { k0t = 0;  k1t = hs - 1; }
        else           { k0t = hs; k1t = qi; }
        partial = true;
    } else {
        qi = 95 - i0; part = 0; k0t = 0; k1t = qi; partial = false;
    }

    const __nv_bfloat16* Kh = g_kh + (size_t)b * SEQT * HD;
    const __nv_bfloat16* Kl = g_kl + (size_t)b * SEQT * HD;
    const __nv_bfloat16* Vh = g_vh + (size_t)b * HD * SEQT;
    const __nv_bfloat16* Vl = g_vl + (size_t)b * HD * SEQT;

    tile_cpb(smu, k0t & 1, k0t, Kh, Kl, Vh, Vl, tid);
    if (k0t + 1 <= k1t)
        tile_cpb(smu, (k0t + 1) & 1, k0t + 1, Kh, Kl, Vh, Vl, tid);

    {
        const __nv_bfloat16* Qh = g_qh + ((size_t)b * SEQT + qi * 64) * HD;
        const __nv_bfloat16* Ql = g_ql + ((size_t)b * SEQT + qi * 64) * HD;
        #pragma unroll
        for (int t = 0; t < 4; t++) {
            int idx = tid + t * 256;
            int pl = idx >> 9, rem = idx & 511, row = rem >> 3, q = rem & 7;
            const __nv_bfloat16* src = (pl ? Ql : Qh) + (size_t)row * HD + q * 8;
            float4 v = *reinterpret_cast<const float4*>(src);
            *reinterpret_cast<float4*>(smu + pl * 2304 + row * PW + q * 4) = v;
        }
    }

    const int r0 = 16 * mw + g;
    float rm0 = -CUDART_INF_F, rm1 = -CUDART_INF_F;
    float rs0 = 0.0f, rs1 = 0.0f;
    float O[4][4];
    #pragma unroll
    for (int nt = 0; nt < 4; nt++)
        #pragma unroll
        for (int i = 0; i < 4; i++) O[nt][i] = 0.0f;

    for (int kt = k0t; kt <= k1t; kt++) {
        uint32_t* Kb = smu + OFF_K + (kt & 1) * 4608;
        uint32_t* Vb = smu + OFF_V + (kt & 1) * 4608;

        if (kt < k1t) asm volatile("cp.async.wait_group 1;" ::: "memory");
        else          asm volatile("cp.async.wait_group 0;" ::: "memory");
        __syncthreads();

        float S[4][4];
        #pragma unroll
        for (int nt = 0; nt < 4; nt++)
            #pragma unroll
            for (int i = 0; i < 4; i++) S[nt][i] = 0.0f;

        #pragma unroll
        for (int ks = 0; ks < 4; ks++) {
            int ab = r0 * PW + 8 * ks + t4;
            uint32_t ah[4], al[4];
            ah[0] = smu[ab];            ah[1] = smu[ab + 8 * PW];
            ah[2] = smu[ab + 4];        ah[3] = smu[ab + 8 * PW + 4];
            al[0] = smu[2304 + ab];     al[1] = smu[2304 + ab + 8 * PW];
            al[2] = smu[2304 + ab + 4]; al[3] = smu[2304 + ab + 8 * PW + 4];
            #pragma unroll
            for (int nt = 0; nt < 4; nt++) {
                int tok = 32 * nw + 8 * nt + g;
                int bb2 = tok * PW + 8 * ks + t4;
                uint32_t bh[2] = {Kb[bb2], Kb[bb2 + 4]};
                uint32_t bl[2] = {Kb[2304 + bb2], Kb[2304 + bb2 + 4]};
                mmabf(S[nt], ah, bh);
                mmabf(S[nt], ah, bl);
                mmabf(S[nt], al, bh);
            }
        }

        if (kt == qi) {
            #pragma unroll
            for (int nt = 0; nt < 4; nt++) {
                int colb = 32 * nw + 8 * nt + 2 * t4;
                if (colb     > r0)     S[nt][0] = -CUDART_INF_F;
                if (colb + 1 > r0)     S[nt][1] = -CUDART_INF_F;
                if (colb     > r0 + 8) S[nt][2] = -CUDART_INF_F;
                if (colb + 1 > r0 + 8) S[nt][3] = -CUDART_INF_F;
            }
        }

        float m0 = fmaxf(fmaxf(S[0][0], S[0][1]), fmaxf(S[1][0], S[1][1]));
        m0 = fmaxf(m0, fmaxf(fmaxf(S[2][0], S[2][1]), fmaxf(S[3][0], S[3][1])));
        float m1 = fmaxf(fmaxf(S[0][2], S[0][3]), fmaxf(S[1][2], S[1][3]));
        m1 = fmaxf(m1, fmaxf(fmaxf(S[2][2], S[2][3]), fmaxf(S[3][2], S[3][3])));
        m0 = fmaxf(m0, __shfl_xor_sync(0xffffffffu, m0, 1));
        m0 = fmaxf(m0, __shfl_xor_sync(0xffffffffu, m0, 2));
        m1 = fmaxf(m1, __shfl_xor_sync(0xffffffffu, m1, 1));
        m1 = fmaxf(m1, __shfl_xor_sync(0xffffffffu, m1, 2));
        if (t4 == 0) {
            Wmx[nw * 64 + r0] = m0;
            Wmx[nw * 64 + r0 + 8] = m1;
        }
        __syncthreads();

        float nm0 = fmaxf(rm0, fmaxf(Wmx[r0], Wmx[64 + r0]));
        float nm1 = fmaxf(rm1, fmaxf(Wmx[r0 + 8], Wmx[64 + r0 + 8]));
        float alpha0 = __expf(rm0 - nm0);
        float alpha1 = __expf(rm1 - nm1);
        rm0 = nm0; rm1 = nm1;

        float sum0 = 0.0f, sum1 = 0.0f;
        #pragma unroll
        for (int nt = 0; nt < 4; nt++) {
            float p00 = __expf(S[nt][0] - nm0);
            float p01 = __expf(S[nt][1] - nm0);
            float p10 = __expf(S[nt][2] - nm1);
            float p11 = __expf(S[nt][3] - nm1);
            sum0 += p00 + p01;
            sum1 += p10 + p11;
            int pc = 16 * nw + 4 * nt + t4;
            uint32_t lo, hi;
            hi = packsplit(p00, p01, lo);
            smu[OFF_PH + r0 * PW + pc] = hi;
            smu[OFF_PL + r0 * PW + pc] = lo;
            hi = packsplit(p10, p11, lo);
            smu[OFF_PH + (r0 + 8) * PW + pc] = hi;
            smu[OFF_PL + (r0 + 8) * PW + pc] = lo;
        }
        sum0 += __shfl_xor_sync(0xffffffffu, sum0, 1);
        sum0 += __shfl_xor_sync(0xffffffffu, sum0, 2);
        sum1 += __shfl_xor_sync(0xffffffffu, sum1, 1);
        sum1 += __shfl_xor_sync(0xffffffffu, sum1, 2);
        if (t4 == 0) {
            Wsm[nw * 64 + r0] = sum0;
            Wsm[nw * 64 + r0 + 8] = sum1;
        }
        __syncthreads();

        rs0 = rs0 * alpha0 + Wsm[r0] + Wsm[64 + r0];
        rs1 = rs1 * alpha1 + Wsm[r0 + 8] + Wsm[64 + r0 + 8];

        #pragma unroll
        for (int nt = 0; nt < 4; nt++) {
            O[nt][0] *= alpha0; O[nt][1] *= alpha0;
            O[nt][2] *= alpha1; O[nt][3] *= alpha1;
        }

        #pragma unroll
        for (int ks = 0; ks < 4; ks++) {
            int ab = r0 * PW + 8 * ks + t4;
            uint32_t ah[4], al[4];
            ah[0] = smu[OFF_PH + ab];     ah[1] = smu[OFF_PH + ab + 8 * PW];
            ah[2] = smu[OFF_PH + ab + 4]; ah[3] = smu[OFF_PH + ab + 8 * PW + 4];
            al[0] = smu[OFF_PL + ab];     al[1] = smu[OFF_PL + ab + 8 * PW];
            al[2] = smu[OFF_PL + ab + 4]; al[3] = smu[OFF_PL + ab + 8 * PW + 4];
            #pragma unroll
            for (int nt = 0; nt < 4; nt++) {
                int d = 32 * nw + 8 * nt + g;
                int vb2 = d * PW + 8 * ks + t4;
                uint32_t bh[2] = {Vb[vb2], Vb[vb2 + 4]};
                uint32_t bl[2] = {Vb[2304 + vb2], Vb[2304 + vb2 + 4]};
                mmabf(O[nt], ah, bh);
                mmabf(O[nt], ah, bl);
                mmabf(O[nt], al, bh);
            }
        }
        __syncthreads();

        if (kt + 2 <= k1t)
            tile_cpb(smu, (kt & 1), kt + 2, Kh, Kl, Vh, Vl, tid);
    }

    if (!partial) {
        float inv0 = 1.0f / rs0, inv1 = 1.0f / rs1;
        #pragma unroll
        for (int nt = 0; nt < 4; nt++) {
            int col = 32 * nw + 8 * nt + 2 * t4;
            size_t row = (size_t)b * SEQT + qi * 64 + r0;
            *reinterpret_cast<float2*>(&out[row * HD + col]) =
                make_float2(O[nt][0] * inv0, O[nt][1] * inv0);
            *reinterpret_cast<float2*>(&out[(row + 8) * HD + col]) =
                make_float2(O[nt][2] * inv1, O[nt][3] * inv1);
        }
    } else {
        int gr = b * SEQT + qi * 64 + r0;
        #pragma unroll
        for (int nt = 0; nt < 4; nt++) {
            int col = 32 * nw + 8 * nt + 2 * t4;
            *reinterpret_cast<float2*>(&g_po[part][(size_t)gr * HD + col]) =
                make_float2(O[nt][0], O[nt][1]);
            *reinterpret_cast<float2*>(&g_po[part][(size_t)(gr + 8) * HD + col]) =
                make_float2(O[nt][2], O[nt][3]);
        }
        if (nw == 0 && t4 == 0) {
            g_pm[part][gr] = rm0;     g_pl[part][gr] = rs0;
            g_pm[part][gr + 8] = rm1; g_pl[part][gr + 8] = rs1;
        }
    }
}

// ---------------------------------------------------------------------------
// Combine split-K partials (rows with qi >= 32). (unchanged)
// ---------------------------------------------------------------------------
__global__ __launch_bounds__(256) void combine_kernel(float* __restrict__ out)
{
    int idx = blockIdx.x * 256 + threadIdx.x;
    int hr = idx >> 4;
    int c4 = (idx & 15) << 2;
    int b = hr >> 11;
    int r = 2048 + (hr & 2047);
    int gr = b * SEQT + r;

    float m0 = g_pm[0][gr], m1 = g_pm[1][gr];
    float M = fmaxf(m0, m1);
    float e0 = __expf(m0 - M), e1 = __expf(m1 - M);
    float den = e0 * g_pl[0][gr] + e1 * g_pl[1][gr];
    float inv = 1.0f / den;

    float4 a = *reinterpret_cast<float4*>(&g_po[0][(size_t)gr * HD + c4]);
    float4 c = *reinterpret_cast<float4*>(&g_po[1][(size_t)gr * HD + c4]);
    float4 o;
    o.x = (e0 * a.x + e1 * c.x) * inv;
    o.y = (e0 * a.y + e1 * c.y) * inv;
    o.z = (e0 * a.z + e1 * c.z) * inv;
    o.w = (e0 * a.w + e1 * c.w) * inv;
    *reinterpret_cast<float4*>(&out[(size_t)gr * HD + c4]) = o;
}

extern "C" void kernel_launch(void* const* d_in, const int* in_sizes, int n_in,
                              void* d_out, int out_size) {
    (void)in_sizes; (void)n_in; (void)out_size;
    const float* x  = (const float*)d_in[0];
    const float* Wk = (const float*)d_in[1];
    const float* Wq = (const float*)d_in[2];
    const float* Wv = (const float*)d_in[3];
    float* out = (float*)d_out;

    wsplit_kernel<<<576, 256>>>(Wq, Wk, Wv);

    cudaFuncSetAttribute(proj_bf16_kernel,
                         cudaFuncAttributeMaxDynamicSharedMemorySize,
                         PJ2_SMEM_BYTES);
    proj_bf16_kernel<<<BT / 128, 256, PJ2_SMEM_BYTES>>>(x);

    cudaFuncSetAttribute(attn_mma_kernel,
                         cudaFuncAttributeMaxDynamicSharedMemorySize,
                         ATTN_SMEM_BYTES);
    dim3 ag(96, BATCH);
    attn_mma_kernel<<<ag, 256, ATTN_SMEM_BYTES>>>(out);

    combine_kernel<<<512, 256>>>(out);
}

// round 9
// speedup vs baseline: 3.6183x; 1.1437x over previous
#include <cuda_runtime.h>
#include <cuda_bf16.h>
#include <math_constants.h>
#include <cstdint>

#define BATCH 4
#define SEQT 4096
#define EMB 768
#define HD 64
#define BT (BATCH * SEQT)

typedef unsigned long long ull;

// Scratch (device globals: no allocation allowed)
__device__ __nv_bfloat16 g_qh[BT * HD], g_ql[BT * HD];
__device__ __nv_bfloat16 g_kh[BT * HD], g_kl[BT * HD];
__device__ __nv_bfloat16 g_vh[BT * HD], g_vl[BT * HD];   // transposed [d][tok]
__device__ __nv_bfloat16 g_wth[3 * 64 * EMB], g_wtl[3 * 64 * EMB];
__device__ float g_po[3][BT * HD];  // split-K partial numerators
__device__ float g_pm[3][BT];       // split-K partial row max
__device__ float g_pl[3][BT];       // split-K partial row sum

__device__ __forceinline__ uint32_t s2u(const void* p) {
    return (uint32_t)__cvta_generic_to_shared(p);
}
__device__ __forceinline__ void cp16(uint32_t dst, const void* src) {
    asm volatile("cp.async.ca.shared.global [%0], [%1], 16;" :: "r"(dst), "l"(src));
}

// ---- bf16 helpers ----
__device__ __forceinline__ void mmabf(float* c, const uint32_t* a, const uint32_t* b) {
    asm volatile(
        "mma.sync.aligned.m16n8k16.row.col.f32.bf16.bf16.f32 "
        "{%0,%1,%2,%3}, {%4,%5,%6,%7}, {%8,%9}, {%0,%1,%2,%3};"
        : "+f"(c[0]), "+f"(c[1]), "+f"(c[2]), "+f"(c[3])
        : "r"(a[0]), "r"(a[1]), "r"(a[2]), "r"(a[3]), "r"(b[0]), "r"(b[1]));
}
__device__ __forceinline__ void bfsplit(float v, __nv_bfloat16& h, __nv_bfloat16& l) {
    h = __float2bfloat16_rn(v);
    l = __float2bfloat16_rn(v - __bfloat162float(h));
}
__device__ __forceinline__ uint32_t bfpack(__nv_bfloat16 a, __nv_bfloat16 b) {
    unsigned short ua = *reinterpret_cast<unsigned short*>(&a);
    unsigned short ub = *reinterpret_cast<unsigned short*>(&b);
    return (uint32_t)ua | ((uint32_t)ub << 16);
}
__device__ __forceinline__ uint32_t packsplit(float a, float b, uint32_t& lopk) {
    __nv_bfloat16 ha, la, hb, lb;
    bfsplit(a, ha, la);
    bfsplit(b, hb, lb);
    lopk = bfpack(la, lb);
    return bfpack(ha, hb);
}

// ---------------------------------------------------------------------------
// W pre-split (unchanged)
// ---------------------------------------------------------------------------
__global__ __launch_bounds__(256) void wsplit_kernel(
    const float* __restrict__ Wq,
    const float* __restrict__ Wk,
    const float* __restrict__ Wv)
{
    int idx = blockIdx.x * 256 + threadIdx.x;
    int mat = idx / (64 * EMB);
    int rem = idx - mat * 64 * EMB;
    int n = rem / EMB;
    int k = rem - n * EMB;
    const float* W = (mat == 0) ? Wq : ((mat == 1) ? Wk : Wv);
    float v = W[(size_t)k * HD + n];
    __nv_bfloat16 h, l;
    bfsplit(v, h, l);
    g_wth[idx] = h;
    g_wtl[idx] = l;
}

// ---------------------------------------------------------------------------
// Fused projection, all-bf16 m16n8k16 3-term. (unchanged from R8)
// ---------------------------------------------------------------------------
#define XF_OFF 0
#define XP_OFF 9216
#define WP_OFF 14336
#define PJ2_SMEM_U32 29696
#define PJ2_SMEM_BYTES (PJ2_SMEM_U32 * 4)

__device__ __forceinline__ void pj2_cp(uint32_t* smu, int buf,
                                       const float* __restrict__ x,
                                       int row0, int k0, int tid)
{
    uint32_t* xf = smu + XF_OFF + buf * 4608;
    #pragma unroll
    for (int t = 0; t < 4; t++) {
        int idx = tid + t * 256;
        int r = idx >> 3, c = idx & 7;
        cp16(s2u(xf + r * 36 + c * 4), &x[(size_t)(row0 + r) * EMB + k0 + c * 4]);
    }
    uint32_t* wp = smu + WP_OFF + buf * 7680;
    #pragma unroll
    for (int t = 0; t < 6; t++) {
        int idx = tid + t * 256;
        int pl = (idx >= 768) ? 1 : 0;
        int rem = idx - pl * 768;
        int row = rem >> 2, chunk = rem & 3;
        const __nv_bfloat16* src =
            (pl ? g_wtl : g_wth) + (size_t)row * EMB + k0 + chunk * 8;
        cp16(s2u(wp + pl * 3840 + row * 20 + chunk * 4), src);
    }
    asm volatile("cp.async.commit_group;" ::: "memory");
}

__global__ __launch_bounds__(256) void proj_bf16_kernel(const float* __restrict__ x)
{
    extern __shared__ uint32_t smu[];
    const int tid = threadIdx.x;
    const int lane = tid & 31;
    const int wid = tid >> 5;
    const int wr = wid >> 1;
    const int wc = wid & 1;
    const int row0 = blockIdx.x * 128;
    const int g = lane >> 2;
    const int t4 = lane & 3;

    float C[2][12][4];
    #pragma unroll
    for (int mt = 0; mt < 2; mt++)
        #pragma unroll
        for (int nt = 0; nt < 12; nt++)
            #pragma unroll
            for (int i = 0; i < 4; i++) C[mt][nt][i] = 0.0f;

    pj2_cp(smu, 0, x, row0, 0, tid);
    pj2_cp(smu, 1, x, row0, 32, tid);

    for (int s = 0; s < 24; s++) {
        const int buf = s & 1;

        if (s < 23) asm volatile("cp.async.wait_group 1;" ::: "memory");
        else        asm volatile("cp.async.wait_group 0;" ::: "memory");
        __syncthreads();

        {
            const uint32_t* xf = smu + XF_OFF + buf * 4608;
            uint32_t* xph = smu + XP_OFF;
            uint32_t* xpl = smu + XP_OFF + 2560;
            #pragma unroll
            for (int t = 0; t < 4; t++) {
                int idx = tid + t * 256;
                int r = idx >> 3, c = idx & 7;
                float4 v = *reinterpret_cast<const float4*>(xf + r * 36 + c * 4);
                uint32_t lo0, lo1;
                uint32_t h0 = packsplit(v.x, v.y, lo0);
                uint32_t h1 = packsplit(v.z, v.w, lo1);
                xph[r * 20 + c * 2] = h0;
                xph[r * 20 + c * 2 + 1] = h1;
                xpl[r * 20 + c * 2] = lo0;
                xpl[r * 20 + c * 2 + 1] = lo1;
            }
        }
        __syncthreads();

        {
            const uint32_t* xph = smu + XP_OFF;
            const uint32_t* xpl = smu + XP_OFF + 2560;
            const uint32_t* wph = smu + WP_OFF + buf * 7680;
            const uint32_t* wpl = wph + 3840;
            #pragma unroll
            for (int ks = 0; ks < 2; ks++) {
                uint32_t ah[2][4], al[2][4];
                #pragma unroll
                for (int mt = 0; mt < 2; mt++) {
                    int ab = (wr * 32 + mt * 16 + g) * 20 + ks * 8 + t4;
                    ah[mt][0] = xph[ab];       ah[mt][1] = xph[ab + 160];
                    ah[mt][2] = xph[ab + 4];   ah[mt][3] = xph[ab + 164];
                    al[mt][0] = xpl[ab];       al[mt][1] = xpl[ab + 160];
                    al[mt][2] = xpl[ab + 4];   al[mt][3] = xpl[ab + 164];
                }
                #pragma unroll
                for (int nt = 0; nt < 12; nt++) {
                    int gcol = wc * 96 + nt * 8 + g;
                    int bb = gcol * 20 + ks * 8 + t4;
                    uint32_t bh[2] = {wph[bb], wph[bb + 4]};
                    uint32_t bl[2] = {wpl[bb], wpl[bb + 4]};
                    #pragma unroll
                    for (int mt = 0; mt < 2; mt++) {
                        mmabf(C[mt][nt], ah[mt], bh);
                        mmabf(C[mt][nt], ah[mt], bl);
                        mmabf(C[mt][nt], al[mt], bh);
                    }
                }
            }
        }
        __syncthreads();

        if (s + 2 < 24)
            pj2_cp(smu, buf, x, row0, (s + 2) * 32, tid);
    }

    #pragma unroll
    for (int mt = 0; mt < 2; mt++) {
        #pragma unroll
        for (int nt = 0; nt < 12; nt++) {
            int gn = wc * 96 + nt * 8;
            int mat = gn >> 6;
            int col = (gn & 63) + t4 * 2;
            int row = row0 + wr * 32 + mt * 16 + g;
            float c0 = C[mt][nt][0], c1 = C[mt][nt][1];
            float c2 = C[mt][nt][2], c3 = C[mt][nt][3];
            if (mat == 0) {
                uint32_t lo, hi;
                hi = packsplit(0.125f * c0, 0.125f * c1, lo);
                *reinterpret_cast<uint32_t*>(&g_qh[(size_t)row * HD + col]) = hi;
                *reinterpret_cast<uint32_t*>(&g_ql[(size_t)row * HD + col]) = lo;
                hi = packsplit(0.125f * c2, 0.125f * c3, lo);
                *reinterpret_cast<uint32_t*>(&g_qh[(size_t)(row + 8) * HD + col]) = hi;
                *reinterpret_cast<uint32_t*>(&g_ql[(size_t)(row + 8) * HD + col]) = lo;
            } else if (mat == 1) {
                uint32_t lo, hi;
                hi = packsplit(c0, c1, lo);
                *reinterpret_cast<uint32_t*>(&g_kh[(size_t)row * HD + col]) = hi;
                *reinterpret_cast<uint32_t*>(&g_kl[(size_t)row * HD + col]) = lo;
                hi = packsplit(c2, c3, lo);
                *reinterpret_cast<uint32_t*>(&g_kh[(size_t)(row + 8) * HD + col]) = hi;
                *reinterpret_cast<uint32_t*>(&g_kl[(size_t)(row + 8) * HD + col]) = lo;
            } else {
                int bb = row >> 12;
                int tok = row & (SEQT - 1);
                size_t b0 = (size_t)(bb * HD + col) * SEQT + tok;
                size_t b1 = b0 + SEQT;
                __nv_bfloat16 h, l;
                bfsplit(c0, h, l); g_vh[b0] = h;     g_vl[b0] = l;
                bfsplit(c1, h, l); g_vh[b1] = h;     g_vl[b1] = l;
                bfsplit(c2, h, l); g_vh[b0 + 8] = h; g_vl[b0 + 8] = l;
                bfsplit(c3, h, l); g_vh[b1 + 8] = h; g_vl[b1 + 8] = l;
            }
        }
    }
}

// ---------------------------------------------------------------------------
// Flash attention (causal), FA2-style: P in registers, per-warp online max,
// rowsum via ones-column mma. grid (120, B):
//   i0<48:  qi = 63 - i0/3, part = i0%3, np=3
//   i0<96:  qi = 47 - (i0-48)/2, part = (i0-48)&1, np=2
//   else:   qi = 23 - (i0-96), np=1
// 8 warps = 4 mw (16 rows) x 2 nw (32-token halves). 2 syncs/tile.
// ---------------------------------------------------------------------------
#define PW 36
#define OFF_K  4608
#define OFF_V  13824
#define OFF_ST 23040            // staging: 64 x 66 fp32
#define ATTN_SMEM_U32 27264
#define ATTN_SMEM_BYTES (ATTN_SMEM_U32 * 4)

__device__ __forceinline__ void tile_cpb(uint32_t* smu, int buf, int kt,
    const __nv_bfloat16* Kh, const __nv_bfloat16* Kl,
    const __nv_bfloat16* Vh, const __nv_bfloat16* Vl, int tid)
{
    uint32_t* kb = smu + OFF_K + buf * 4608;
    uint32_t* vb = smu + OFF_V + buf * 4608;
    #pragma unroll
    for (int t = 0; t < 4; t++) {
        int idx = tid + t * 256;
        int pl = idx >> 9, rem = idx & 511, tok = rem >> 3, q = rem & 7;
        const __nv_bfloat16* s = (pl ? Kl : Kh) + (size_t)(kt * 64 + tok) * HD + q * 8;
        cp16(s2u(kb + pl * 2304 + tok * PW + q * 4), s);
    }
    #pragma unroll
    for (int t = 0; t < 4; t++) {
        int idx = tid + t * 256;
        int pl = idx >> 9, rem = idx & 511, d = rem >> 3, q = rem & 7;
        const __nv_bfloat16* s = (pl ? Vl : Vh) + (size_t)d * SEQT + kt * 64 + q * 8;
        cp16(s2u(vb + pl * 2304 + d * PW + q * 4), s);
    }
    asm volatile("cp.async.commit_group;" ::: "memory");
}

__global__ __launch_bounds__(256, 2) void attn_mma_kernel(float* __restrict__ out)
{
    extern __shared__ uint32_t smu[];

    const int tid = threadIdx.x;
    const int lane = tid & 31;
    const int wid = tid >> 5;
    const int mw = wid >> 1;
    const int nw = wid & 1;
    const int g = lane >> 2;
    const int t4 = lane & 3;
    const int b = blockIdx.y;
    const int i0 = blockIdx.x;

    int qi, part, np;
    if (i0 < 48)      { qi = 63 - i0 / 3;        part = i0 % 3;        np = 3; }
    else if (i0 < 96) { int t = i0 - 48; qi = 47 - t / 2; part = t & 1; np = 2; }
    else              { qi = 23 - (i0 - 96);     part = 0;             np = 1; }
    const int ntl = qi + 1;
    const int k0t = (part * ntl) / np;
    const int k1t = ((part + 1) * ntl) / np - 1;
    const bool partial = (np > 1);

    const __nv_bfloat16* Kh = g_kh + (size_t)b * SEQT * HD;
    const __nv_bfloat16* Kl = g_kl + (size_t)b * SEQT * HD;
    const __nv_bfloat16* Vh = g_vh + (size_t)b * HD * SEQT;
    const __nv_bfloat16* Vl = g_vl + (size_t)b * HD * SEQT;

    tile_cpb(smu, k0t & 1, k0t, Kh, Kl, Vh, Vl, tid);
    if (k0t + 1 <= k1t)
        tile_cpb(smu, (k0t + 1) & 1, k0t + 1, Kh, Kl, Vh, Vl, tid);

    {
        const __nv_bfloat16* Qh = g_qh + ((size_t)b * SEQT + qi * 64) * HD;
        const __nv_bfloat16* Ql = g_ql + ((size_t)b * SEQT + qi * 64) * HD;
        #pragma unroll
        for (int t = 0; t < 4; t++) {
            int idx = tid + t * 256;
            int pl = idx >> 9, rem = idx & 511, row = rem >> 3, q = rem & 7;
            const __nv_bfloat16* src = (pl ? Ql : Qh) + (size_t)row * HD + q * 8;
            float4 v = *reinterpret_cast<const float4*>(src);
            *reinterpret_cast<float4*>(smu + pl * 2304 + row * PW + q * 4) = v;
        }
    }

    const int r0 = 16 * mw + g;
    float rm0 = -CUDART_INF_F, rm1 = -CUDART_INF_F;
    float O[8][4];
    float Osum[4];
    #pragma unroll
    for (int nt = 0; nt < 8; nt++)
        #pragma unroll
        for (int i = 0; i < 4; i++) O[nt][i] = 0.0f;
    #pragma unroll
    for (int i = 0; i < 4; i++) Osum[i] = 0.0f;

    const uint32_t onesv = (g == 0) ? 0x3F803F80u : 0u;
    const uint32_t bones[2] = {onesv, onesv};

    for (int kt = k0t; kt <= k1t; kt++) {
        uint32_t* Kb = smu + OFF_K + (kt & 1) * 4608;
        uint32_t* Vb = smu + OFF_V + (kt & 1) * 4608;

        if (kt < k1t) asm volatile("cp.async.wait_group 1;" ::: "memory");
        else          asm volatile("cp.async.wait_group 0;" ::: "memory");
        __syncthreads();

        // ---- S = Q K^T (3-term bf16) ----
        float S[4][4];
        #pragma unroll
        for (int nt = 0; nt < 4; nt++)
            #pragma unroll
            for (int i = 0; i < 4; i++) S[nt][i] = 0.0f;

        #pragma unroll
        for (int ks = 0; ks < 4; ks++) {
            int ab = r0 * PW + 8 * ks + t4;
            uint32_t ah[4], al[4];
            ah[0] = smu[ab];            ah[1] = smu[ab + 8 * PW];
            ah[2] = smu[ab + 4];        ah[3] = smu[ab + 8 * PW + 4];
            al[0] = smu[2304 + ab];     al[1] = smu[2304 + ab + 8 * PW];
            al[2] = smu[2304 + ab + 4]; al[3] = smu[2304 + ab + 8 * PW + 4];
            #pragma unroll
            for (int nt = 0; nt < 4; nt++) {
                int tok = 32 * nw + 8 * nt + g;
                int bb2 = tok * PW + 8 * ks + t4;
                uint32_t bh[2] = {Kb[bb2], Kb[bb2 + 4]};
                uint32_t bl[2] = {Kb[2304 + bb2], Kb[2304 + bb2 + 4]};
                mmabf(S[nt], ah, bh);
                mmabf(S[nt], ah, bl);
                mmabf(S[nt], al, bh);
            }
        }

        // ---- causal mask ----
        if (kt == qi) {
            #pragma unroll
            for (int nt = 0; nt < 4; nt++) {
                int colb = 32 * nw + 8 * nt + 2 * t4;
                if (colb     > r0)     S[nt][0] = -CUDART_INF_F;
                if (colb + 1 > r0)     S[nt][1] = -CUDART_INF_F;
                if (colb     > r0 + 8) S[nt][2] = -CUDART_INF_F;
                if (colb + 1 > r0 + 8) S[nt][3] = -CUDART_INF_F;
            }
        }

        // ---- per-warp online softmax (no cross-warp traffic) ----
        float wm0 = fmaxf(fmaxf(S[0][0], S[0][1]), fmaxf(S[1][0], S[1][1]));
        wm0 = fmaxf(wm0, fmaxf(fmaxf(S[2][0], S[2][1]), fmaxf(S[3][0], S[3][1])));
        float wm1 = fmaxf(fmaxf(S[0][2], S[0][3]), fmaxf(S[1][2], S[1][3]));
        wm1 = fmaxf(wm1, fmaxf(fmaxf(S[2][2], S[2][3]), fmaxf(S[3][2], S[3][3])));
        wm0 = fmaxf(wm0, __shfl_xor_sync(0xffffffffu, wm0, 1));
        wm0 = fmaxf(wm0, __shfl_xor_sync(0xffffffffu, wm0, 2));
        wm1 = fmaxf(wm1, __shfl_xor_sync(0xffffffffu, wm1, 1));
        wm1 = fmaxf(wm1, __shfl_xor_sync(0xffffffffu, wm1, 2));

        float nm0 = fmaxf(rm0, wm0);
        float nm1 = fmaxf(rm1, wm1);
        float ne0 = (nm0 == -CUDART_INF_F) ? 0.0f : nm0;
        float ne1 = (nm1 == -CUDART_INF_F) ? 0.0f : nm1;
        float alpha0 = __expf(rm0 - ne0);
        float alpha1 = __expf(rm1 - ne1);
        rm0 = nm0; rm1 = nm1;

        // ---- p = exp(s - ne), pack S C-frags -> P A-frags (registers) ----
        uint32_t ph[2][4], pl2[2][4];
        #pragma unroll
        for (int ks = 0; ks < 2; ks++) {
            float p00 = __expf(S[2 * ks][0] - ne0);
            float p01 = __expf(S[2 * ks][1] - ne0);
            float p10 = __expf(S[2 * ks][2] - ne1);
            float p11 = __expf(S[2 * ks][3] - ne1);
            float p20 = __expf(S[2 * ks + 1][0] - ne0);
            float p21 = __expf(S[2 * ks + 1][1] - ne0);
            float p30 = __expf(S[2 * ks + 1][2] - ne1);
            float p31 = __expf(S[2 * ks + 1][3] - ne1);
            ph[ks][0] = packsplit(p00, p01, pl2[ks][0]);
            ph[ks][1] = packsplit(p10, p11, pl2[ks][1]);
            ph[ks][2] = packsplit(p20, p21, pl2[ks][2]);
            ph[ks][3] = packsplit(p30, p31, pl2[ks][3]);
        }

        // ---- rescale O and rowsum ----
        #pragma unroll
        for (int nt = 0; nt < 8; nt++) {
            O[nt][0] *= alpha0; O[nt][1] *= alpha0;
            O[nt][2] *= alpha1; O[nt][3] *= alpha1;
        }
        Osum[0] *= alpha0; Osum[2] *= alpha1;

        // ---- O += P @ V over this warp's 32-token half; rowsum via ones ----
        #pragma unroll
        for (int ks = 0; ks < 2; ks++) {
            mmabf(Osum, ph[ks], bones);
            mmabf(Osum, pl2[ks], bones);
            #pragma unroll
            for (int nt = 0; nt < 8; nt++) {
                int d = 8 * nt + g;
                int vb2 = d * PW + 16 * nw + 8 * ks + t4;
                uint32_t bh[2] = {Vb[vb2], Vb[vb2 + 4]};
                uint32_t bl[2] = {Vb[2304 + vb2], Vb[2304 + vb2 + 4]};
                mmabf(O[nt], ph[ks], bh);
                mmabf(O[nt], ph[ks], bl);
                mmabf(O[nt], pl2[ks], bh);
            }
        }
        __syncthreads();

        if (kt + 2 <= k1t)
            tile_cpb(smu, (kt & 1), kt + 2, Kh, Kl, Vh, Vl, tid);
    }

    // ---- epilogue: merge the two nw halves (softmax-combine), then write ----
    float* stg = reinterpret_cast<float*>(smu + OFF_ST);  // [64][66]
    if (nw == 1) {
        #pragma unroll
        for (int nt = 0; nt < 8; nt++) {
            int c = 8 * nt + 2 * t4;
            stg[r0 * 66 + c] = O[nt][0];
            stg[r0 * 66 + c + 1] = O[nt][1];
            stg[(r0 + 8) * 66 + c] = O[nt][2];
            stg[(r0 + 8) * 66 + c + 1] = O[nt][3];
        }
        if (t4 == 0) {
            stg[r0 * 66 + 64] = Osum[0];       stg[r0 * 66 + 65] = rm0;
            stg[(r0 + 8) * 66 + 64] = Osum[2]; stg[(r0 + 8) * 66 + 65] = rm1;
        }
    }
    __syncthreads();
    if (nw == 0) {
        float rsS0 = __shfl_sync(0xffffffffu, Osum[0], lane & 28);
        float rsS1 = __shfl_sync(0xffffffffu, Osum[2], lane & 28);
        float ors0 = stg[r0 * 66 + 64],       orm0 = stg[r0 * 66 + 65];
        float ors1 = stg[(r0 + 8) * 66 + 64], orm1 = stg[(r0 + 8) * 66 + 65];
        float M0 = fmaxf(rm0, orm0), M1 = fmaxf(rm1, orm1);
        float es0 = __expf(rm0 - M0), eo0 = __expf(orm0 - M0);
        float es1 = __expf(rm1 - M1), eo1 = __expf(orm1 - M1);
        float rt0 = es0 * rsS0 + eo0 * ors0;
        float rt1 = es1 * rsS1 + eo1 * ors1;

        if (!partial) {
            float iv0 = 1.0f / rt0, iv1 = 1.0f / rt1;
            size_t row = (size_t)b * SEQT + qi * 64 + r0;
            #pragma unroll
            for (int nt = 0; nt < 8; nt++) {
                int c = 8 * nt + 2 * t4;
                float a0 = es0 * O[nt][0] + eo0 * stg[r0 * 66 + c];
                float a1 = es0 * O[nt][1] + eo0 * stg[r0 * 66 + c + 1];
                float a2 = es1 * O[nt][2] + eo1 * stg[(r0 + 8) * 66 + c];
                float a3 = es1 * O[nt][3] + eo1 * stg[(r0 + 8) * 66 + c + 1];
                *reinterpret_cast<float2*>(&out[row * HD + c]) =
                    make_float2(a0 * iv0, a1 * iv0);
                *reinterpret_cast<float2*>(&out[(row + 8) * HD + c]) =
                    make_float2(a2 * iv1, a3 * iv1);
            }
        } else {
            int gr = b * SEQT + qi * 64 + r0;
            #pragma unroll
            for (int nt = 0; nt < 8; nt++) {
                int c = 8 * nt + 2 * t4;
                float a0 = es0 * O[nt][0] + eo0 * stg[r0 * 66 + c];
                float a1 = es0 * O[nt][1] + eo0 * stg[r0 * 66 + c + 1];
                float a2 = es1 * O[nt][2] + eo1 * stg[(r0 + 8) * 66 + c];
                float a3 = es1 * O[nt][3] + eo1 * stg[(r0 + 8) * 66 + c + 1];
                *reinterpret_cast<float2*>(&g_po[part][(size_t)gr * HD + c]) =
                    make_float2(a0, a1);
                *reinterpret_cast<float2*>(&g_po[part][(size_t)(gr + 8) * HD + c]) =
                    make_float2(a2, a3);
            }
            if (t4 == 0) {
                g_pm[part][gr] = M0;     g_pl[part][gr] = rt0;
                g_pm[part][gr + 8] = M1; g_pl[part][gr + 8] = rt1;
            }
        }
    }
}

// ---------------------------------------------------------------------------
// Combine split-K partials: rows with qi >= 24 (local row >= 1536).
// np = 3 for row >= 3072, else 2. 4 x 2560 rows x 16 float4 -> 640 blocks.
// ---------------------------------------------------------------------------
__global__ __launch_bounds__(256) void combine_kernel(float* __restrict__ out)
{
    int idx = blockIdx.x * 256 + threadIdx.x;
    int hr = idx >> 4;
    int c4 = (idx & 15) << 2;
    int b = hr / 2560;
    int r = 1536 + (hr - b * 2560);
    int gr = b * SEQT + r;
    int np = (r >= 3072) ? 3 : 2;

    float M = fmaxf(g_pm[0][gr], g_pm[1][gr]);
    if (np == 3) M = fmaxf(M, g_pm[2][gr]);

    float den = 0.0f;
    float ax = 0.0f, ay = 0.0f, az = 0.0f, aw = 0.0f;
    #pragma unroll
    for (int j = 0; j < 3; j++) {
        if (j < np) {
            float e = __expf(g_pm[j][gr] - M);
            den += e * g_pl[j][gr];
            float4 v = *reinterpret_cast<float4*>(&g_po[j][(size_t)gr * HD + c4]);
            ax += e * v.x; ay += e * v.y; az += e * v.z; aw += e * v.w;
        }
    }
    float inv = 1.0f / den;
    *reinterpret_cast<float4*>(&out[(size_t)gr * HD + c4]) =
        make_float4(ax * inv, ay * inv, az * inv, aw * inv);
}

extern "C" void kernel_launch(void* const* d_in, const int* in_sizes, int n_in,
                              void* d_out, int out_size) {
    (void)in_sizes; (void)n_in; (void)out_size;
    const float* x  = (const float*)d_in[0];
    const float* Wk = (const float*)d_in[1];
    const float* Wq = (const float*)d_in[2];
    const float* Wv = (const float*)d_in[3];
    float* out = (float*)d_out;

    wsplit_kernel<<<576, 256>>>(Wq, Wk, Wv);

    cudaFuncSetAttribute(proj_bf16_kernel,
                         cudaFuncAttributeMaxDynamicSharedMemorySize,
                         PJ2_SMEM_BYTES);
    proj_bf16_kernel<<<BT / 128, 256, PJ2_SMEM_BYTES>>>(x);

    cudaFuncSetAttribute(attn_mma_kernel,
                         cudaFuncAttributeMaxDynamicSharedMemorySize,
                         ATTN_SMEM_BYTES);
    dim3 ag(120, BATCH);
    attn_mma_kernel<<<ag, 256, ATTN_SMEM_BYTES>>>(out);

    combine_kernel<<<640, 256>>>(out);
}

// round 10
// speedup vs baseline: 3.6855x; 1.0186x over previous
#include <cuda_runtime.h>
#include <cuda_bf16.h>
#include <math_constants.h>
#include <cstdint>

#define BATCH 4
#define SEQT 4096
#define EMB 768
#define HD 64
#define BT (BATCH * SEQT)

typedef unsigned long long ull;

// Scratch (device globals: no allocation allowed)
__device__ __nv_bfloat16 g_qh[BT * HD], g_ql[BT * HD];
__device__ __nv_bfloat16 g_kh[BT * HD], g_kl[BT * HD];
__device__ __nv_bfloat16 g_vh[BT * HD], g_vl[BT * HD];   // transposed [d][tok]
__device__ __nv_bfloat16 g_wth[3 * 64 * EMB], g_wtl[3 * 64 * EMB];
__device__ float g_po[4][BT * HD];  // split-K partial numerators
__device__ float g_pm[4][BT];       // split-K partial row max
__device__ float g_pl[4][BT];       // split-K partial row sum

__device__ __forceinline__ uint32_t s2u(const void* p) {
    return (uint32_t)__cvta_generic_to_shared(p);
}
__device__ __forceinline__ void cp16(uint32_t dst, const void* src) {
    asm volatile("cp.async.ca.shared.global [%0], [%1], 16;" :: "r"(dst), "l"(src));
}

// ---- bf16 helpers ----
__device__ __forceinline__ void mmabf(float* c, const uint32_t* a, const uint32_t* b) {
    asm volatile(
        "mma.sync.aligned.m16n8k16.row.col.f32.bf16.bf16.f32 "
        "{%0,%1,%2,%3}, {%4,%5,%6,%7}, {%8,%9}, {%0,%1,%2,%3};"
        : "+f"(c[0]), "+f"(c[1]), "+f"(c[2]), "+f"(c[3])
        : "r"(a[0]), "r"(a[1]), "r"(a[2]), "r"(a[3]), "r"(b[0]), "r"(b[1]));
}
__device__ __forceinline__ void bfsplit(float v, __nv_bfloat16& h, __nv_bfloat16& l) {
    h = __float2bfloat16_rn(v);
    l = __float2bfloat16_rn(v - __bfloat162float(h));
}
__device__ __forceinline__ uint32_t bfpack(__nv_bfloat16 a, __nv_bfloat16 b) {
    unsigned short ua = *reinterpret_cast<unsigned short*>(&a);
    unsigned short ub = *reinterpret_cast<unsigned short*>(&b);
    return (uint32_t)ua | ((uint32_t)ub << 16);
}
__device__ __forceinline__ uint32_t packsplit(float a, float b, uint32_t& lopk) {
    __nv_bfloat16 ha, la, hb, lb;
    bfsplit(a, ha, la);
    bfsplit(b, hb, lb);
    lopk = bfpack(la, lb);
    return bfpack(ha, hb);
}

// ---------------------------------------------------------------------------
// W pre-split (unchanged)
// ---------------------------------------------------------------------------
__global__ __launch_bounds__(256) void wsplit_kernel(
    const float* __restrict__ Wq,
    const float* __restrict__ Wk,
    const float* __restrict__ Wv)
{
    int idx = blockIdx.x * 256 + threadIdx.x;
    int mat = idx / (64 * EMB);
    int rem = idx - mat * 64 * EMB;
    int n = rem / EMB;
    int k = rem - n * EMB;
    const float* W = (mat == 0) ? Wq : ((mat == 1) ? Wk : Wv);
    float v = W[(size_t)k * HD + n];
    __nv_bfloat16 h, l;
    bfsplit(v, h, l);
    g_wth[idx] = h;
    g_wtl[idx] = l;
}

// ---------------------------------------------------------------------------
// Fused projection, all-bf16 m16n8k16 3-term. M=64/CTA, 256 CTAs, 2/SM.
// 8 warps: wr=wid>>1 (16 rows), wc=wid&1 (96 cols).
// ---------------------------------------------------------------------------
#define XF_OFF 0          // 2 x 64*36 u32 fp32 x staging
#define XP_OFF 4608       // hi 64*20, lo 64*20
#define WP_OFF 7168       // 2 bufs x (hi 192*20 + lo 192*20)
#define PJ2_SMEM_U32 22528
#define PJ2_SMEM_BYTES (PJ2_SMEM_U32 * 4)

__device__ __forceinline__ void pj2_cp(uint32_t* smu, int buf,
                                       const float* __restrict__ x,
                                       int row0, int k0, int tid)
{
    uint32_t* xf = smu + XF_OFF + buf * 2304;
    #pragma unroll
    for (int t = 0; t < 2; t++) {
        int idx = tid + t * 256;
        int r = idx >> 3, c = idx & 7;
        cp16(s2u(xf + r * 36 + c * 4), &x[(size_t)(row0 + r) * EMB + k0 + c * 4]);
    }
    uint32_t* wp = smu + WP_OFF + buf * 7680;
    #pragma unroll
    for (int t = 0; t < 6; t++) {
        int idx = tid + t * 256;
        int pl = (idx >= 768) ? 1 : 0;
        int rem = idx - pl * 768;
        int row = rem >> 2, chunk = rem & 3;
        const __nv_bfloat16* src =
            (pl ? g_wtl : g_wth) + (size_t)row * EMB + k0 + chunk * 8;
        cp16(s2u(wp + pl * 3840 + row * 20 + chunk * 4), src);
    }
    asm volatile("cp.async.commit_group;" ::: "memory");
}

__global__ __launch_bounds__(256, 2) void proj_bf16_kernel(const float* __restrict__ x)
{
    extern __shared__ uint32_t smu[];
    const int tid = threadIdx.x;
    const int lane = tid & 31;
    const int wid = tid >> 5;
    const int wr = wid >> 1;
    const int wc = wid & 1;
    const int row0 = blockIdx.x * 64;
    const int g = lane >> 2;
    const int t4 = lane & 3;

    float C[12][4];
    #pragma unroll
    for (int nt = 0; nt < 12; nt++)
        #pragma unroll
        for (int i = 0; i < 4; i++) C[nt][i] = 0.0f;

    pj2_cp(smu, 0, x, row0, 0, tid);
    pj2_cp(smu, 1, x, row0, 32, tid);

    for (int s = 0; s < 24; s++) {
        const int buf = s & 1;

        if (s < 23) asm volatile("cp.async.wait_group 1;" ::: "memory");
        else        asm volatile("cp.async.wait_group 0;" ::: "memory");
        __syncthreads();

        // Batched convert: fp32 x tile -> bf16 hi/lo planes
        {
            const uint32_t* xf = smu + XF_OFF + buf * 2304;
            uint32_t* xph = smu + XP_OFF;
            uint32_t* xpl = smu + XP_OFF + 1280;
            #pragma unroll
            for (int t = 0; t < 2; t++) {
                int idx = tid + t * 256;
                int r = idx >> 3, c = idx & 7;
                float4 v = *reinterpret_cast<const float4*>(xf + r * 36 + c * 4);
                uint32_t lo0, lo1;
                uint32_t h0 = packsplit(v.x, v.y, lo0);
                uint32_t h1 = packsplit(v.z, v.w, lo1);
                xph[r * 20 + c * 2] = h0;
                xph[r * 20 + c * 2 + 1] = h1;
                xpl[r * 20 + c * 2] = lo0;
                xpl[r * 20 + c * 2 + 1] = lo1;
            }
        }
        __syncthreads();

        {
            const uint32_t* xph = smu + XP_OFF;
            const uint32_t* xpl = smu + XP_OFF + 1280;
            const uint32_t* wph = smu + WP_OFF + buf * 7680;
            const uint32_t* wpl = wph + 3840;
            #pragma unroll
            for (int ks = 0; ks < 2; ks++) {
                uint32_t ah[4], al[4];
                int ab = (wr * 16 + g) * 20 + ks * 8 + t4;
                ah[0] = xph[ab];       ah[1] = xph[ab + 160];
                ah[2] = xph[ab + 4];   ah[3] = xph[ab + 164];
                al[0] = xpl[ab];       al[1] = xpl[ab + 160];
                al[2] = xpl[ab + 4];   al[3] = xpl[ab + 164];
                #pragma unroll
                for (int nt = 0; nt < 12; nt++) {
                    int gcol = wc * 96 + nt * 8 + g;
                    int bb = gcol * 20 + ks * 8 + t4;
                    uint32_t bh[2] = {wph[bb], wph[bb + 4]};
                    uint32_t bl[2] = {wpl[bb], wpl[bb + 4]};
                    mmabf(C[nt], ah, bh);
                    mmabf(C[nt], ah, bl);
                    mmabf(C[nt], al, bh);
                }
            }
        }
        __syncthreads();

        if (s + 2 < 24)
            pj2_cp(smu, buf, x, row0, (s + 2) * 32, tid);
    }

    // Epilogue: bf16 hi/lo plane stores (q,k row-major; v transposed; q*0.125)
    #pragma unroll
    for (int nt = 0; nt < 12; nt++) {
        int gn = wc * 96 + nt * 8;
        int mat = gn >> 6;
        int col = (gn & 63) + t4 * 2;
        int row = row0 + wr * 16 + g;
        float c0 = C[nt][0], c1 = C[nt][1];
        float c2 = C[nt][2], c3 = C[nt][3];
        if (mat == 0) {
            uint32_t lo, hi;
            hi = packsplit(0.125f * c0, 0.125f * c1, lo);
            *reinterpret_cast<uint32_t*>(&g_qh[(size_t)row * HD + col]) = hi;
            *reinterpret_cast<uint32_t*>(&g_ql[(size_t)row * HD + col]) = lo;
            hi = packsplit(0.125f * c2, 0.125f * c3, lo);
            *reinterpret_cast<uint32_t*>(&g_qh[(size_t)(row + 8) * HD + col]) = hi;
            *reinterpret_cast<uint32_t*>(&g_ql[(size_t)(row + 8) * HD + col]) = lo;
        } else if (mat == 1) {
            uint32_t lo, hi;
            hi = packsplit(c0, c1, lo);
            *reinterpret_cast<uint32_t*>(&g_kh[(size_t)row * HD + col]) = hi;
            *reinterpret_cast<uint32_t*>(&g_kl[(size_t)row * HD + col]) = lo;
            hi = packsplit(c2, c3, lo);
            *reinterpret_cast<uint32_t*>(&g_kh[(size_t)(row + 8) * HD + col]) = hi;
            *reinterpret_cast<uint32_t*>(&g_kl[(size_t)(row + 8) * HD + col]) = lo;
        } else {
            int bb = row >> 12;
            int tok = row & (SEQT - 1);
            size_t b0 = (size_t)(bb * HD + col) * SEQT + tok;
            size_t b1 = b0 + SEQT;
            __nv_bfloat16 h, l;
            bfsplit(c0, h, l); g_vh[b0] = h;     g_vl[b0] = l;
            bfsplit(c1, h, l); g_vh[b1] = h;     g_vl[b1] = l;
            bfsplit(c2, h, l); g_vh[b0 + 8] = h; g_vl[b0 + 8] = l;
            bfsplit(c3, h, l); g_vh[b1 + 8] = h; g_vl[b1 + 8] = l;
        }
    }
}

// ---------------------------------------------------------------------------
// Flash attention (causal), FA2: 128-row Q tiles, each warp owns 16 full rows.
// grid (74, B), one full wave at 2 CTA/SM:
//   i0<16: qi=31-i0/4, np=4 | i0<46: qi=27-(i0-16)/3, np=3
//   i0<66: qi=17-(i0-46)/2, np=2 | else qi=7-(i0-66), np=1
// K-range in 64-token tiles: ntl = 2qi+2; diag tiles 2qi, 2qi+1.
// ---------------------------------------------------------------------------
#define PW 36
#define OFF_K 9216          // 2 bufs x 4608 (hi 2304 + lo 2304)
#define OFF_V 18432
#define ATTN_SMEM_U32 27648
#define ATTN_SMEM_BYTES (ATTN_SMEM_U32 * 4)

__device__ __forceinline__ void tile_cpb(uint32_t* smu, int buf, int kt,
    const __nv_bfloat16* Kh, const __nv_bfloat16* Kl,
    const __nv_bfloat16* Vh, const __nv_bfloat16* Vl, int tid)
{
    uint32_t* kb = smu + OFF_K + buf * 4608;
    uint32_t* vb = smu + OFF_V + buf * 4608;
    #pragma unroll
    for (int t = 0; t < 4; t++) {
        int idx = tid + t * 256;
        int pl = idx >> 9, rem = idx & 511, tok = rem >> 3, q = rem & 7;
        const __nv_bfloat16* s = (pl ? Kl : Kh) + (size_t)(kt * 64 + tok) * HD + q * 8;
        cp16(s2u(kb + pl * 2304 + tok * PW + q * 4), s);
    }
    #pragma unroll
    for (int t = 0; t < 4; t++) {
        int idx = tid + t * 256;
        int pl = idx >> 9, rem = idx & 511, d = rem >> 3, q = rem & 7;
        const __nv_bfloat16* s = (pl ? Vl : Vh) + (size_t)d * SEQT + kt * 64 + q * 8;
        cp16(s2u(vb + pl * 2304 + d * PW + q * 4), s);
    }
    asm volatile("cp.async.commit_group;" ::: "memory");
}

__global__ __launch_bounds__(256, 2) void attn_mma_kernel(float* __restrict__ out)
{
    extern __shared__ uint32_t smu[];

    const int tid = threadIdx.x;
    const int lane = tid & 31;
    const int wid = tid >> 5;           // 0..7 = m-warp
    const int g = lane >> 2;
    const int t4 = lane & 3;
    const int b = blockIdx.y;
    const int i0 = blockIdx.x;

    int qi, part, np;
    if (i0 < 16)      { qi = 31 - (i0 >> 2);            part = i0 & 3;  np = 4; }
    else if (i0 < 46) { int t = i0 - 16; qi = 27 - t / 3; part = t % 3; np = 3; }
    else if (i0 < 66) { int t = i0 - 46; qi = 17 - (t >> 1); part = t & 1; np = 2; }
    else              { qi = 7 - (i0 - 66);             part = 0;       np = 1; }
    const int ntl = 2 * qi + 2;
    const int k0t = (part * ntl) / np;
    const int k1t = ((part + 1) * ntl) / np - 1;
    const bool partial = (np > 1);
    const int diag0 = ntl - 2, diag1 = ntl - 1;

    const __nv_bfloat16* Kh = g_kh + (size_t)b * SEQT * HD;
    const __nv_bfloat16* Kl = g_kl + (size_t)b * SEQT * HD;
    const __nv_bfloat16* Vh = g_vh + (size_t)b * HD * SEQT;
    const __nv_bfloat16* Vl = g_vl + (size_t)b * HD * SEQT;

    tile_cpb(smu, k0t & 1, k0t, Kh, Kl, Vh, Vl, tid);
    if (k0t + 1 <= k1t)
        tile_cpb(smu, (k0t + 1) & 1, k0t + 1, Kh, Kl, Vh, Vl, tid);

    // Q tile: 128 rows, hi plane at smu[0..4607], lo at smu[4608..]
    {
        const __nv_bfloat16* Qh = g_qh + ((size_t)b * SEQT + qi * 128) * HD;
        const __nv_bfloat16* Ql = g_ql + ((size_t)b * SEQT + qi * 128) * HD;
        #pragma unroll
        for (int t = 0; t < 8; t++) {
            int idx = tid + t * 256;
            int pl = idx >> 10, rem = idx & 1023, row = rem >> 3, q = rem & 7;
            const __nv_bfloat16* src = (pl ? Ql : Qh) + (size_t)row * HD + q * 8;
            float4 v = *reinterpret_cast<const float4*>(src);
            *reinterpret_cast<float4*>(smu + pl * 4608 + row * PW + q * 4) = v;
        }
    }

    const int r0 = 16 * wid + g;
    float rm0 = -CUDART_INF_F, rm1 = -CUDART_INF_F;
    float O[8][4];
    float Osum[4];
    #pragma unroll
    for (int nt = 0; nt < 8; nt++)
        #pragma unroll
        for (int i = 0; i < 4; i++) O[nt][i] = 0.0f;
    #pragma unroll
    for (int i = 0; i < 4; i++) Osum[i] = 0.0f;

    const uint32_t onesv = (g == 0) ? 0x3F803F80u : 0u;
    const uint32_t bones[2] = {onesv, onesv};

    for (int kt = k0t; kt <= k1t; kt++) {
        uint32_t* Kb = smu + OFF_K + (kt & 1) * 4608;
        uint32_t* Vb = smu + OFF_V + (kt & 1) * 4608;

        if (kt < k1t) asm volatile("cp.async.wait_group 1;" ::: "memory");
        else          asm volatile("cp.async.wait_group 0;" ::: "memory");
        __syncthreads();

        // ---- S = Q K^T over 64 tokens (3-term bf16) ----
        float S[8][4];
        #pragma unroll
        for (int nt = 0; nt < 8; nt++)
            #pragma unroll
            for (int i = 0; i < 4; i++) S[nt][i] = 0.0f;

        #pragma unroll
        for (int ks = 0; ks < 4; ks++) {
            int ab = r0 * PW + 8 * ks + t4;
            uint32_t ah[4], al[4];
            ah[0] = smu[ab];            ah[1] = smu[ab + 8 * PW];
            ah[2] = smu[ab + 4];        ah[3] = smu[ab + 8 * PW + 4];
            al[0] = smu[4608 + ab];     al[1] = smu[4608 + ab + 8 * PW];
            al[2] = smu[4608 + ab + 4]; al[3] = smu[4608 + ab + 8 * PW + 4];
            #pragma unroll
            for (int nt = 0; nt < 8; nt++) {
                int tok = 8 * nt + g;
                int bb2 = tok * PW + 8 * ks + t4;
                uint32_t bh[2] = {Kb[bb2], Kb[bb2 + 4]};
                uint32_t bl[2] = {Kb[2304 + bb2], Kb[2304 + bb2 + 4]};
                mmabf(S[nt], ah, bh);
                mmabf(S[nt], ah, bl);
                mmabf(S[nt], al, bh);
            }
        }

        // ---- causal mask on the two diagonal tiles ----
        if (kt == diag0 || kt == diag1) {
            int coff = (kt == diag1) ? 64 : 0;
            #pragma unroll
            for (int nt = 0; nt < 8; nt++) {
                int colb = 8 * nt + 2 * t4 + coff;
                if (colb     > r0)     S[nt][0] = -CUDART_INF_F;
                if (colb + 1 > r0)     S[nt][1] = -CUDART_INF_F;
                if (colb     > r0 + 8) S[nt][2] = -CUDART_INF_F;
                if (colb + 1 > r0 + 8) S[nt][3] = -CUDART_INF_F;
            }
        }

        // ---- per-warp online softmax (full rows; no cross-warp traffic) ----
        float wm0 = fmaxf(fmaxf(S[0][0], S[0][1]), fmaxf(S[1][0], S[1][1]));
        wm0 = fmaxf(wm0, fmaxf(fmaxf(S[2][0], S[2][1]), fmaxf(S[3][0], S[3][1])));
        wm0 = fmaxf(wm0, fmaxf(fmaxf(S[4][0], S[4][1]), fmaxf(S[5][0], S[5][1])));
        wm0 = fmaxf(wm0, fmaxf(fmaxf(S[6][0], S[6][1]), fmaxf(S[7][0], S[7][1])));
        float wm1 = fmaxf(fmaxf(S[0][2], S[0][3]), fmaxf(S[1][2], S[1][3]));
        wm1 = fmaxf(wm1, fmaxf(fmaxf(S[2][2], S[2][3]), fmaxf(S[3][2], S[3][3])));
        wm1 = fmaxf(wm1, fmaxf(fmaxf(S[4][2], S[4][3]), fmaxf(S[5][2], S[5][3])));
        wm1 = fmaxf(wm1, fmaxf(fmaxf(S[6][2], S[6][3]), fmaxf(S[7][2], S[7][3])));
        wm0 = fmaxf(wm0, __shfl_xor_sync(0xffffffffu, wm0, 1));
        wm0 = fmaxf(wm0, __shfl_xor_sync(0xffffffffu, wm0, 2));
        wm1 = fmaxf(wm1, __shfl_xor_sync(0xffffffffu, wm1, 1));
        wm1 = fmaxf(wm1, __shfl_xor_sync(0xffffffffu, wm1, 2));

        float nm0 = fmaxf(rm0, wm0);
        float nm1 = fmaxf(rm1, wm1);
        float ne0 = (nm0 == -CUDART_INF_F) ? 0.0f : nm0;
        float ne1 = (nm1 == -CUDART_INF_F) ? 0.0f : nm1;
        float alpha0 = __expf(rm0 - ne0);
        float alpha1 = __expf(rm1 - ne1);
        rm0 = nm0; rm1 = nm1;

        // ---- p = exp(s - ne), pack S C-frags -> P A-frags (registers) ----
        uint32_t ph[4][4], pl2[4][4];
        #pragma unroll
        for (int ks = 0; ks < 4; ks++) {
            float p00 = __expf(S[2 * ks][0] - ne0);
            float p01 = __expf(S[2 * ks][1] - ne0);
            float p10 = __expf(S[2 * ks][2] - ne1);
            float p11 = __expf(S[2 * ks][3] - ne1);
            float p20 = __expf(S[2 * ks + 1][0] - ne0);
            float p21 = __expf(S[2 * ks + 1][1] - ne0);
            float p30 = __expf(S[2 * ks + 1][2] - ne1);
            float p31 = __expf(S[2 * ks + 1][3] - ne1);
            ph[ks][0] = packsplit(p00, p01, pl2[ks][0]);
            ph[ks][1] = packsplit(p10, p11, pl2[ks][1]);
            ph[ks][2] = packsplit(p20, p21, pl2[ks][2]);
            ph[ks][3] = packsplit(p30, p31, pl2[ks][3]);
        }

        // ---- rescale O / rowsum ----
        #pragma unroll
        for (int nt = 0; nt < 8; nt++) {
            O[nt][0] *= alpha0; O[nt][1] *= alpha0;
            O[nt][2] *= alpha1; O[nt][3] *= alpha1;
        }
        Osum[0] *= alpha0; Osum[2] *= alpha1;

        // ---- O += P @ V over all 64 tokens; rowsum via ones-column ----
        #pragma unroll
        for (int ks = 0; ks < 4; ks++) {
            mmabf(Osum, ph[ks], bones);
            mmabf(Osum, pl2[ks], bones);
            #pragma unroll
            for (int nt = 0; nt < 8; nt++) {
                int d = 8 * nt + g;
                int vb2 = d * PW + 8 * ks + t4;
                uint32_t bh[2] = {Vb[vb2], Vb[vb2 + 4]};
                uint32_t bl[2] = {Vb[2304 + vb2], Vb[2304 + vb2 + 4]};
                mmabf(O[nt], ph[ks], bh);
                mmabf(O[nt], ph[ks], bl);
                mmabf(O[nt], pl2[ks], bh);
            }
        }
        __syncthreads();

        if (kt + 2 <= k1t)
            tile_cpb(smu, (kt & 1), kt + 2, Kh, Kl, Vh, Vl, tid);
    }

    // ---- epilogue: rows complete per warp; no merge needed ----
    float rs0 = __shfl_sync(0xffffffffu, Osum[0], lane & 28);
    float rs1 = __shfl_sync(0xffffffffu, Osum[2], lane & 28);

    if (!partial) {
        float iv0 = 1.0f / rs0, iv1 = 1.0f / rs1;
        size_t row = (size_t)b * SEQT + qi * 128 + r0;
        #pragma unroll
        for (int nt = 0; nt < 8; nt++) {
            int c = 8 * nt + 2 * t4;
            *reinterpret_cast<float2*>(&out[row * HD + c]) =
                make_float2(O[nt][0] * iv0, O[nt][1] * iv0);
            *reinterpret_cast<float2*>(&out[(row + 8) * HD + c]) =
                make_float2(O[nt][2] * iv1, O[nt][3] * iv1);
        }
    } else {
        int gr = b * SEQT + qi * 128 + r0;
        #pragma unroll
        for (int nt = 0; nt < 8; nt++) {
            int c = 8 * nt + 2 * t4;
            *reinterpret_cast<float2*>(&g_po[part][(size_t)gr * HD + c]) =
                make_float2(O[nt][0], O[nt][1]);
            *reinterpret_cast<float2*>(&g_po[part][(size_t)(gr + 8) * HD + c]) =
                make_float2(O[nt][2], O[nt][3]);
        }
        if (t4 == 0) {
            g_pm[part][gr] = rm0;     g_pl[part][gr] = rs0;
            g_pm[part][gr + 8] = rm1; g_pl[part][gr + 8] = rs1;
        }
    }
}

// ---------------------------------------------------------------------------
// Combine split-K partials: rows with qi >= 8 (local row >= 1024).
// np = 4 for row >= 3584, 3 for row >= 2304, else 2.
// 4 batches x 3072 rows x 16 float4 -> 768 blocks.
// ---------------------------------------------------------------------------
__global__ __launch_bounds__(256) void combine_kernel(float* __restrict__ out)
{
    int idx = blockIdx.x * 256 + threadIdx.x;
    int hr = idx >> 4;
    int c4 = (idx & 15) << 2;
    int b = hr / 3072;
    int r = 1024 + (hr - b * 3072);
    int gr = b * SEQT + r;
    int np = (r >= 3584) ? 4 : ((r >= 2304) ? 3 : 2);

    float M = fmaxf(g_pm[0][gr], g_pm[1][gr]);
    if (np >= 3) M = fmaxf(M, g_pm[2][gr]);
    if (np == 4) M = fmaxf(M, g_pm[3][gr]);

    float den = 0.0f;
    float ax = 0.0f, ay = 0.0f, az = 0.0f, aw = 0.0f;
    #pragma unroll
    for (int j = 0; j < 4; j++) {
        if (j < np) {
            float e = __expf(g_pm[j][gr] - M);
            den += e * g_pl[j][gr];
            float4 v = *reinterpret_cast<float4*>(&g_po[j][(size_t)gr * HD + c4]);
            ax += e * v.x; ay += e * v.y; az += e * v.z; aw += e * v.w;
        }
    }
    float inv = 1.0f / den;
    *reinterpret_cast<float4*>(&out[(size_t)gr * HD + c4]) =
        make_float4(ax * inv, ay * inv, az * inv, aw * inv);
}

extern "C" void kernel_launch(void* const* d_in, const int* in_sizes, int n_in,
                              void* d_out, int out_size) {
    (void)in_sizes; (void)n_in; (void)out_size;
    const float* x  = (const float*)d_in[0];
    const float* Wk = (const float*)d_in[1];
    const float* Wq = (const float*)d_in[2];
    const float* Wv = (const float*)d_in[3];
    float* out = (float*)d_out;

    wsplit_kernel<<<576, 256>>>(Wq, Wk, Wv);

    cudaFuncSetAttribute(proj_bf16_kernel,
                         cudaFuncAttributeMaxDynamicSharedMemorySize,
                         PJ2_SMEM_BYTES);
    proj_bf16_kernel<<<BT / 64, 256, PJ2_SMEM_BYTES>>>(x);

    cudaFuncSetAttribute(attn_mma_kernel,
                         cudaFuncAttributeMaxDynamicSharedMemorySize,
                         ATTN_SMEM_BYTES);
    dim3 ag(74, BATCH);
    attn_mma_kernel<<<ag, 256, ATTN_SMEM_BYTES>>>(out);

    combine_kernel<<<768, 256>>>(out);
}